// round 5
// baseline (speedup 1.0000x reference)
#include <cuda_runtime.h>
#include <cuda_bf16.h>
#include <cstdint>

// ---------------------------------------------------------------------------
// GraphSAGE forward on GB300 — mma.sync bf16x3 GEMMs with persistent bf16
// hi/lo activations (no in-loop conversion) + CSR mean aggregation.
// ---------------------------------------------------------------------------
namespace {
constexpr int Nn = 100000;   // nodes
constexpr int Ee = 1600000;  // edges
constexpr int Hc = 128;      // hidden channels
constexpr int Oc = 64;       // out channels
constexpr int NT = (Nn + 127) / 128;  // 782 row tiles
// weight scratch layout (combined [Wl|Wr] per layer, row-major [n][k])
constexpr int WOFF_IN = 0;                 // inProj 128x128
constexpr int WOFF_H = 16384;              // hidden i: +i*32768 (128x256)
constexpr int WOFF_O = 16384 + 3 * 32768;  // out 64x256
constexpr int WTOT = WOFF_O + 64 * 256;    // 131072
}

// ------------------------- static device scratch ---------------------------
__device__ float g_inp[(size_t)Nn * Hc];          // pre-relu inProj (residual)
__device__ __nv_bfloat16 g_xh[(size_t)Nn * Hc];   // x hi
__device__ __nv_bfloat16 g_xl[(size_t)Nn * Hc];   // x lo
__device__ __nv_bfloat16 g_hh0[(size_t)Nn * Hc];  // h hi ping
__device__ __nv_bfloat16 g_hl0[(size_t)Nn * Hc];  // h lo ping
__device__ __nv_bfloat16 g_hh1[(size_t)Nn * Hc];  // h hi pong
__device__ __nv_bfloat16 g_hl1[(size_t)Nn * Hc];  // h lo pong
__device__ __nv_bfloat16 g_mh[(size_t)Nn * Hc];   // mean hi
__device__ __nv_bfloat16 g_ml[(size_t)Nn * Hc];   // mean lo
__device__ float g_invdeg[Nn];
__device__ int   g_cnt[Nn];
__device__ int   g_rowptr[Nn + 1];
__device__ int   g_cursor[Nn];
__device__ int   g_csr[Ee];
__device__ __nv_bfloat16 g_Bhi[WTOT];
__device__ __nv_bfloat16 g_Blo[WTOT];

// ------------------------------ PTX helpers --------------------------------
__device__ __forceinline__ uint32_t smem_to_u32(const void* p) {
    uint32_t a;
    asm("{ .reg .u64 t; cvta.to.shared.u64 t, %1; cvt.u32.u64 %0, t; }"
        : "=r"(a) : "l"(p));
    return a;
}
__device__ __forceinline__ void ldsm_x4(uint32_t* r, uint32_t addr) {
    asm volatile("ldmatrix.sync.aligned.m8n8.x4.shared.b16 {%0,%1,%2,%3}, [%4];"
                 : "=r"(r[0]), "=r"(r[1]), "=r"(r[2]), "=r"(r[3]) : "r"(addr));
}
__device__ __forceinline__ void mma_bf16(float* c, const uint32_t* a, const uint32_t* b) {
    asm volatile(
        "mma.sync.aligned.m16n8k16.row.col.f32.bf16.bf16.f32 "
        "{%0,%1,%2,%3}, {%4,%5,%6,%7}, {%8,%9}, {%0,%1,%2,%3};"
        : "+f"(c[0]), "+f"(c[1]), "+f"(c[2]), "+f"(c[3])
        : "r"(a[0]), "r"(a[1]), "r"(a[2]), "r"(a[3]), "r"(b[0]), "r"(b[1]));
}
__device__ __forceinline__ uint32_t pack_hilo(float a, float b, uint32_t& lopack) {
    __nv_bfloat16 ha = __float2bfloat16(a);
    __nv_bfloat16 hb = __float2bfloat16(b);
    float la = a - __bfloat162float(ha);
    float lb = b - __bfloat162float(hb);
    __nv_bfloat16 lah = __float2bfloat16(la);
    __nv_bfloat16 lbh = __float2bfloat16(lb);
    lopack = ((uint32_t)__bfloat16_as_ushort(lbh) << 16) | (uint32_t)__bfloat16_as_ushort(lah);
    return ((uint32_t)__bfloat16_as_ushort(hb) << 16) | (uint32_t)__bfloat16_as_ushort(ha);
}
__device__ __forceinline__ float2 bf2_to_f2(uint32_t u) {
    __nv_bfloat162 b = *reinterpret_cast<__nv_bfloat162*>(&u);
    return __bfloat1622float2(b);
}

// ----------------------------- CSR construction ----------------------------
__global__ void k_zero_cnt() {
    int i = blockIdx.x * blockDim.x + threadIdx.x;
    if (i < Nn) g_cnt[i] = 0;
}
__global__ void k_hist(const int* __restrict__ dst) {
    int i = blockIdx.x * blockDim.x + threadIdx.x;
    if (i < Ee) atomicAdd(&g_cnt[dst[i]], 1);
}
__global__ void k_scan() {
    __shared__ int sums[1024];
    const int t = threadIdx.x;
    const int CH = 128;
    const int base = t * CH;
    int s = 0;
    for (int i = 0; i < CH; i++) {
        int idx = base + i;
        if (idx < Nn) s += g_cnt[idx];
    }
    sums[t] = s;
    __syncthreads();
    int mine = s;
    for (int d = 1; d < 1024; d <<= 1) {
        int v = (t >= d) ? sums[t - d] : 0;
        __syncthreads();
        sums[t] += v;
        __syncthreads();
    }
    int run = sums[t] - mine;
    for (int i = 0; i < CH; i++) {
        int idx = base + i;
        if (idx < Nn) {
            int c = g_cnt[idx];
            g_rowptr[idx] = run;
            g_cursor[idx] = run;
            g_invdeg[idx] = 1.0f / fmaxf((float)c, 1.0f);
            run += c;
        }
    }
    if (t == 0) g_rowptr[Nn] = Ee;
}
__global__ void k_fill(const int* __restrict__ src, const int* __restrict__ dst) {
    int i = blockIdx.x * blockDim.x + threadIdx.x;
    if (i < Ee) {
        int d = dst[i];
        int pos = atomicAdd(&g_cursor[d], 1);
        g_csr[pos] = src[i];
    }
}

// ---------------- mean aggregation (warp / node, bf16 hi/lo) ---------------
__global__ __launch_bounds__(256) void k_agg(const __nv_bfloat16* __restrict__ hh,
                                             const __nv_bfloat16* __restrict__ hl) {
    int warp = (blockIdx.x * blockDim.x + threadIdx.x) >> 5;
    if (warp >= Nn) return;
    int lane = threadIdx.x & 31;
    int b = g_rowptr[warp];
    int e = g_rowptr[warp + 1];
    float a0 = 0.f, a1 = 0.f, a2 = 0.f, a3 = 0.f;
    int i = b;
    for (; i + 1 < e; i += 2) {
        int s0 = g_csr[i], s1 = g_csr[i + 1];
        uint2 uh0 = *(const uint2*)(hh + (size_t)s0 * Hc + lane * 4);
        uint2 ul0 = *(const uint2*)(hl + (size_t)s0 * Hc + lane * 4);
        uint2 uh1 = *(const uint2*)(hh + (size_t)s1 * Hc + lane * 4);
        uint2 ul1 = *(const uint2*)(hl + (size_t)s1 * Hc + lane * 4);
        float2 f;
        f = bf2_to_f2(uh0.x); a0 += f.x; a1 += f.y;
        f = bf2_to_f2(uh0.y); a2 += f.x; a3 += f.y;
        f = bf2_to_f2(ul0.x); a0 += f.x; a1 += f.y;
        f = bf2_to_f2(ul0.y); a2 += f.x; a3 += f.y;
        f = bf2_to_f2(uh1.x); a0 += f.x; a1 += f.y;
        f = bf2_to_f2(uh1.y); a2 += f.x; a3 += f.y;
        f = bf2_to_f2(ul1.x); a0 += f.x; a1 += f.y;
        f = bf2_to_f2(ul1.y); a2 += f.x; a3 += f.y;
    }
    if (i < e) {
        int s0 = g_csr[i];
        uint2 uh0 = *(const uint2*)(hh + (size_t)s0 * Hc + lane * 4);
        uint2 ul0 = *(const uint2*)(hl + (size_t)s0 * Hc + lane * 4);
        float2 f;
        f = bf2_to_f2(uh0.x); a0 += f.x; a1 += f.y;
        f = bf2_to_f2(uh0.y); a2 += f.x; a3 += f.y;
        f = bf2_to_f2(ul0.x); a0 += f.x; a1 += f.y;
        f = bf2_to_f2(ul0.y); a2 += f.x; a3 += f.y;
    }
    float id = g_invdeg[warp];
    a0 *= id; a1 *= id; a2 *= id; a3 *= id;
    uint32_t lo0, lo1;
    uint32_t hi0 = pack_hilo(a0, a1, lo0);
    uint32_t hi1 = pack_hilo(a2, a3, lo1);
    *(uint2*)(g_mh + (size_t)warp * Hc + lane * 4) = make_uint2(hi0, hi1);
    *(uint2*)(g_ml + (size_t)warp * Hc + lane * 4) = make_uint2(lo0, lo1);
}

// ------------------------ conversions (weights, x) --------------------------
__global__ void k_wconv(const float* __restrict__ Wp, const float* __restrict__ Wl_h,
                        const float* __restrict__ Wr_h, const float* __restrict__ Wl_o,
                        const float* __restrict__ Wr_o) {
    int i = blockIdx.x * blockDim.x + threadIdx.x;
    if (i >= WTOT) return;
    float w;
    if (i < WOFF_H) {
        w = Wp[i];
    } else if (i < WOFF_O) {
        int j = i - WOFF_H;
        int layer = j / 32768;
        int r = j % 32768;
        int n = r >> 8, k = r & 255;
        w = (k < 128) ? Wl_h[layer * 16384 + n * 128 + k]
                      : Wr_h[layer * 16384 + n * 128 + (k - 128)];
    } else {
        int r = i - WOFF_O;
        int n = r >> 8, k = r & 255;
        w = (k < 128) ? Wl_o[n * 128 + k] : Wr_o[n * 128 + (k - 128)];
    }
    __nv_bfloat16 h = __float2bfloat16(w);
    g_Bhi[i] = h;
    g_Blo[i] = __float2bfloat16(w - __bfloat162float(h));
}

__global__ void k_xconv(const float* __restrict__ x) {
    int i = blockIdx.x * blockDim.x + threadIdx.x;  // float4 index
    if (i >= Nn * Hc / 4) return;
    float4 f = ((const float4*)x)[i];
    uint32_t lo0, lo1;
    uint32_t hi0 = pack_hilo(f.x, f.y, lo0);
    uint32_t hi1 = pack_hilo(f.z, f.w, lo1);
    ((uint2*)g_xh)[i] = make_uint2(hi0, hi1);
    ((uint2*)g_xl)[i] = make_uint2(lo0, lo1);
}

// ----------------------- mma.sync bf16x3 fused GEMM ------------------------
// out[m, :NOUT] = [A0|A1][m, :KTOT] @ W[:NOUT, :KTOT]^T + bias (+epilogue)
// A given as persistent bf16 hi/lo arrays (row stride 128 per phase).
// W pre-split bf16 hi/lo in global, staged once to smem.
// 512 threads = 16 warps as 8m x 2n; warp tile m16 x n(NOUT/2).
template <int NOUT, int KTOT, bool TWO, bool RELU, bool RESID, bool PRE, bool WM, bool WBF>
__global__ __launch_bounds__(512) void k_mgemm(
    const __nv_bfloat16* __restrict__ A0h, const __nv_bfloat16* __restrict__ A0l,
    const __nv_bfloat16* __restrict__ A1h, const __nv_bfloat16* __restrict__ A1l,
    const __nv_bfloat16* __restrict__ Bh, const __nv_bfloat16* __restrict__ Bl,
    const float* __restrict__ bias, const float* __restrict__ resid,
    float* __restrict__ outm, float* __restrict__ outp,
    __nv_bfloat16* __restrict__ outh, __nv_bfloat16* __restrict__ outl) {
    extern __shared__ char smem[];
    constexpr int AST = KTOT + 8;               // bf16 row stride (conflict-free LDSM)
    constexpr int OFF_BH = 0;
    constexpr int OFF_BL = NOUT * AST * 2;
    constexpr int OFF_BIAS = 2 * NOUT * AST * 2;
    constexpr int NI = NOUT / 16;               // n8 tiles per warp (8 or 4)
    constexpr int NW = NI * 8;

    const uint32_t sm32 = smem_to_u32(smem);
    const int tid = threadIdx.x;
    const int lane = tid & 31;
    const int wid = tid >> 5;
    const int wm = wid & 7;       // m block (16 rows)
    const int wn = wid >> 3;      // n block (NW cols)
    const int m0 = blockIdx.x * 128;

    // ---- stage B hi/lo once ----
    {
        constexpr int GPR = KTOT / 8;            // 16B granules per row
        constexpr int NG = NOUT * GPR;
        for (int g = tid; g < NG; g += 512) {
            int n = g / GPR;
            int kc = (g % GPR) * 8;
            char* dh = smem + OFF_BH + ((size_t)n * AST + kc) * 2;
            char* dl = smem + OFF_BL + ((size_t)n * AST + kc) * 2;
            *(uint4*)dh = *(const uint4*)(Bh + (size_t)n * KTOT + kc);
            *(uint4*)dl = *(const uint4*)(Bl + (size_t)n * KTOT + kc);
        }
        if (tid < NOUT) *(float*)(smem + OFF_BIAS + tid * 4) = bias[tid];
    }
    __syncthreads();

    // ldmatrix lane address for B
    const int r8 = lane & 7, q = lane >> 3;
    const uint32_t boff =
        (uint32_t)(((wn * NW) + (q >> 1) * 8 + r8) * AST + (q & 1) * 8) * 2;

    // A rows for this lane
    const int row0 = m0 + wm * 16 + (lane >> 2);
    const int row1 = row0 + 8;
    const bool v0 = row0 < Nn, v1 = row1 < Nn;
    const int col0 = (lane & 3) * 2;

    float acc[NI][4];
#pragma unroll
    for (int ni = 0; ni < NI; ni++)
#pragma unroll
        for (int c = 0; c < 4; c++) acc[ni][c] = 0.f;

    const size_t r0off = (size_t)row0 * 128 + col0;
    const size_t r1off = (size_t)row1 * 128 + col0;

#pragma unroll
    for (int p = 0; p < (TWO ? 2 : 1); p++) {
        const __nv_bfloat16* __restrict__ Ah = p ? A1h : A0h;
        const __nv_bfloat16* __restrict__ Al = p ? A1l : A0l;
#pragma unroll
        for (int k8 = 0; k8 < 8; k8++) {
            const int kk = p * 8 + k8;
            const int kb = k8 * 16;
            // ---- A fragments straight from global bf16 ----
            uint32_t ah[4], al[4];
            ah[0] = v0 ? *(const uint32_t*)(Ah + r0off + kb) : 0u;
            ah[1] = v1 ? *(const uint32_t*)(Ah + r1off + kb) : 0u;
            ah[2] = v0 ? *(const uint32_t*)(Ah + r0off + kb + 8) : 0u;
            ah[3] = v1 ? *(const uint32_t*)(Ah + r1off + kb + 8) : 0u;
            al[0] = v0 ? *(const uint32_t*)(Al + r0off + kb) : 0u;
            al[1] = v1 ? *(const uint32_t*)(Al + r1off + kb) : 0u;
            al[2] = v0 ? *(const uint32_t*)(Al + r0off + kb + 8) : 0u;
            al[3] = v1 ? *(const uint32_t*)(Al + r1off + kb + 8) : 0u;
            // ---- B fragments (hi & lo) via ldmatrix ----
            uint32_t bh[NI / 2][4], bl[NI / 2][4];
#pragma unroll
            for (int nt = 0; nt < NI / 2; nt++) {
                ldsm_x4(bh[nt], sm32 + OFF_BH + boff + nt * 16 * AST * 2 + kk * 32);
                ldsm_x4(bl[nt], sm32 + OFF_BL + boff + nt * 16 * AST * 2 + kk * 32);
            }
            // ---- 3 correction passes ----
#pragma unroll
            for (int ni = 0; ni < NI; ni++) mma_bf16(acc[ni], ah, &bh[ni >> 1][(ni & 1) * 2]);
#pragma unroll
            for (int ni = 0; ni < NI; ni++) mma_bf16(acc[ni], ah, &bl[ni >> 1][(ni & 1) * 2]);
#pragma unroll
            for (int ni = 0; ni < NI; ni++) mma_bf16(acc[ni], al, &bh[ni >> 1][(ni & 1) * 2]);
        }
    }

    // ------------------------------ epilogue -------------------------------
    const float* biasS = (const float*)(smem + OFF_BIAS);
#pragma unroll
    for (int ni = 0; ni < NI; ni++) {
        const int col = wn * NW + ni * 8 + col0;
        const float b0 = biasS[col], b1 = biasS[col + 1];
#pragma unroll
        for (int half = 0; half < 2; half++) {
            const int row = half ? row1 : row0;
            if (row >= Nn) continue;
            float x0 = acc[ni][half * 2 + 0] + b0;
            float x1 = acc[ni][half * 2 + 1] + b1;
            const size_t off = (size_t)row * NOUT + col;
            if (PRE) *(float2*)(outp + off) = make_float2(x0, x1);
            if (RELU) { x0 = fmaxf(x0, 0.f); x1 = fmaxf(x1, 0.f); }
            if (RESID) {
                float2 rr = *(const float2*)(resid + off);
                x0 = fmaf(0.2f, rr.x, x0);
                x1 = fmaf(0.2f, rr.y, x1);
            }
            if (WM) *(float2*)(outm + off) = make_float2(x0, x1);
            if (WBF) {
                uint32_t lo;
                uint32_t hi = pack_hilo(x0, x1, lo);
                *(uint32_t*)(outh + off) = hi;
                *(uint32_t*)(outl + off) = lo;
            }
        }
    }
}

// ------------------------------ log-softmax --------------------------------
__global__ __launch_bounds__(256) void k_lsm(float* __restrict__ out) {
    int warp = (blockIdx.x * blockDim.x + threadIdx.x) >> 5;
    if (warp >= Nn) return;
    int lane = threadIdx.x & 31;
    float2 v = *(float2*)(out + (size_t)warp * Oc + lane * 2);
    float m = fmaxf(v.x, v.y);
#pragma unroll
    for (int o = 16; o; o >>= 1) m = fmaxf(m, __shfl_xor_sync(0xFFFFFFFFu, m, o));
    float s = expf(v.x - m) + expf(v.y - m);
#pragma unroll
    for (int o = 16; o; o >>= 1) s += __shfl_xor_sync(0xFFFFFFFFu, s, o);
    float l = m + logf(s);
    v.x -= l;
    v.y -= l;
    *(float2*)(out + (size_t)warp * Oc + lane * 2) = v;
}

// ------------------------------- launcher ----------------------------------
extern "C" void kernel_launch(void* const* d_in, const int* in_sizes, int n_in,
                              void* d_out, int out_size) {
    const float* x    = (const float*)d_in[0];
    const int*   ei   = (const int*)d_in[1];
    const float* Wp   = (const float*)d_in[2];
    const float* bp   = (const float*)d_in[3];
    const float* Wl_h = (const float*)d_in[4];
    const float* bl_h = (const float*)d_in[5];
    const float* Wr_h = (const float*)d_in[6];
    const float* Wl_o = (const float*)d_in[7];
    const float* bl_o = (const float*)d_in[8];
    const float* Wr_o = (const float*)d_in[9];
    const int* src = ei;
    const int* dst = ei + Ee;
    float* out = (float*)d_out;

    float* p_inp;
    cudaGetSymbolAddress((void**)&p_inp, g_inp);
    __nv_bfloat16 *p_xh, *p_xl, *p_hh0, *p_hl0, *p_hh1, *p_hl1, *p_mh, *p_ml, *p_bhi, *p_blo;
    cudaGetSymbolAddress((void**)&p_xh, g_xh);
    cudaGetSymbolAddress((void**)&p_xl, g_xl);
    cudaGetSymbolAddress((void**)&p_hh0, g_hh0);
    cudaGetSymbolAddress((void**)&p_hl0, g_hl0);
    cudaGetSymbolAddress((void**)&p_hh1, g_hh1);
    cudaGetSymbolAddress((void**)&p_hl1, g_hl1);
    cudaGetSymbolAddress((void**)&p_mh, g_mh);
    cudaGetSymbolAddress((void**)&p_ml, g_ml);
    cudaGetSymbolAddress((void**)&p_bhi, g_Bhi);
    cudaGetSymbolAddress((void**)&p_blo, g_Blo);

    auto gemm_in  = k_mgemm<128, 128, false, true, false, true, false, true>;
    auto gemm_hid = k_mgemm<128, 256, true, true, true, false, false, true>;
    auto gemm_out = k_mgemm<64, 256, true, false, false, false, true, false>;
    const int SM_IN  = 2 * 128 * 136 * 2 + 512;  // 70144
    const int SM_HID = 2 * 128 * 264 * 2 + 512;  // 135680
    const int SM_OUT = 2 * 64 * 264 * 2 + 512;   // 68096
    cudaFuncSetAttribute(gemm_in, cudaFuncAttributeMaxDynamicSharedMemorySize, SM_IN);
    cudaFuncSetAttribute(gemm_hid, cudaFuncAttributeMaxDynamicSharedMemorySize, SM_HID);
    cudaFuncSetAttribute(gemm_out, cudaFuncAttributeMaxDynamicSharedMemorySize, SM_OUT);

    // Launch order chosen so ncu's captured launch (index 5) is gemm_in.
    k_zero_cnt<<<(Nn + 255) / 256, 256>>>();                                   // 0
    k_hist<<<(Ee + 255) / 256, 256>>>(dst);                                    // 1
    k_wconv<<<(WTOT + 255) / 256, 256>>>(Wp, Wl_h, Wr_h, Wl_o, Wr_o);          // 2
    k_xconv<<<(Nn * Hc / 4 + 255) / 256, 256>>>(x);                            // 3
    k_scan<<<1, 1024>>>();                                                     // 4
    // inProj: g_inp = x@Wp^T + bp (pre-relu), h0 = relu -> bf16 hi/lo
    gemm_in<<<NT, 512, SM_IN>>>(p_xh, p_xl, nullptr, nullptr,                  // 5
                                p_bhi + WOFF_IN, p_blo + WOFF_IN, bp, nullptr,
                                nullptr, p_inp, p_hh0, p_hl0);
    k_fill<<<(Ee + 255) / 256, 256>>>(src, dst);                               // 6

    const int ga = ((Nn * 32) + 255) / 256;

    __nv_bfloat16 *hh = p_hh0, *hl = p_hl0, *nh = p_hh1, *nl = p_hl1;
    for (int i = 0; i < 3; i++) {
        k_agg<<<ga, 256>>>(hh, hl);
        gemm_hid<<<NT, 512, SM_HID>>>(p_mh, p_ml, hh, hl,
                                      p_bhi + WOFF_H + i * 32768, p_blo + WOFF_H + i * 32768,
                                      bl_h + (size_t)i * 128, p_inp,
                                      nullptr, nullptr, nh, nl);
        __nv_bfloat16* t;
        t = hh; hh = nh; nh = t;
        t = hl; hl = nl; nl = t;
    }

    k_agg<<<ga, 256>>>(hh, hl);
    gemm_out<<<NT, 512, SM_OUT>>>(p_mh, p_ml, hh, hl,
                                  p_bhi + WOFF_O, p_blo + WOFF_O, bl_o, nullptr,
                                  out, nullptr, nullptr, nullptr);
    k_lsm<<<ga, 256>>>(out);
}

// round 6
// speedup vs baseline: 1.0970x; 1.0970x over previous
#include <cuda_runtime.h>
#include <cuda_bf16.h>
#include <cstdint>

// ---------------------------------------------------------------------------
// GraphSAGE forward on GB300 — mma.sync bf16x3 GEMMs over packed hi/lo
// activations (uint2 {hi2,lo2} pairs), 2-CTA occupancy, CSR mean aggregation.
// ---------------------------------------------------------------------------
namespace {
constexpr int Nn = 100000;   // nodes
constexpr int Ee = 1600000;  // edges
constexpr int Hc = 128;      // hidden channels
constexpr int Oc = 64;       // out channels
constexpr int NP = 100096;   // padded rows (multiple of 128)
constexpr int NT2 = NP / 64; // 1564 CTA tiles (m64)
// weight scratch layout (combined [Wl|Wr] per layer, row-major [n][k])
constexpr int WOFF_IN = 0;                 // inProj 128x128
constexpr int WOFF_H = 16384;              // hidden i: +i*32768 (128x256)
constexpr int WOFF_O = 16384 + 3 * 32768;  // out 64x256
constexpr int WTOT = WOFF_O + 64 * 256;    // 131072
}

// ------------------------- static device scratch ---------------------------
__device__ float g_inp[(size_t)NP * Hc];    // pre-relu inProj (residual)
__device__ uint2 g_xp[(size_t)NP * 64];     // x packed hi/lo
__device__ uint2 g_hp0[(size_t)NP * 64];    // h packed ping
__device__ uint2 g_hp1[(size_t)NP * 64];    // h packed pong
__device__ uint2 g_mp[(size_t)NP * 64];     // mean packed
__device__ float g_invdeg[Nn];
__device__ int   g_cnt[Nn];
__device__ int   g_rowptr[Nn + 1];
__device__ int   g_cursor[Nn];
__device__ int   g_csr[Ee];
__device__ __nv_bfloat16 g_Bhi[WTOT];
__device__ __nv_bfloat16 g_Blo[WTOT];

// ------------------------------ PTX helpers --------------------------------
__device__ __forceinline__ uint32_t smem_to_u32(const void* p) {
    uint32_t a;
    asm("{ .reg .u64 t; cvta.to.shared.u64 t, %1; cvt.u32.u64 %0, t; }"
        : "=r"(a) : "l"(p));
    return a;
}
__device__ __forceinline__ void ldsm_x4(uint32_t* r, uint32_t addr) {
    asm volatile("ldmatrix.sync.aligned.m8n8.x4.shared.b16 {%0,%1,%2,%3}, [%4];"
                 : "=r"(r[0]), "=r"(r[1]), "=r"(r[2]), "=r"(r[3]) : "r"(addr));
}
__device__ __forceinline__ void mma_bf16(float* c, const uint32_t* a, const uint32_t* b) {
    asm volatile(
        "mma.sync.aligned.m16n8k16.row.col.f32.bf16.bf16.f32 "
        "{%0,%1,%2,%3}, {%4,%5,%6,%7}, {%8,%9}, {%0,%1,%2,%3};"
        : "+f"(c[0]), "+f"(c[1]), "+f"(c[2]), "+f"(c[3])
        : "r"(a[0]), "r"(a[1]), "r"(a[2]), "r"(a[3]), "r"(b[0]), "r"(b[1]));
}
__device__ __forceinline__ uint32_t pack_hilo(float a, float b, uint32_t& lopack) {
    __nv_bfloat16 ha = __float2bfloat16(a);
    __nv_bfloat16 hb = __float2bfloat16(b);
    float la = a - __bfloat162float(ha);
    float lb = b - __bfloat162float(hb);
    __nv_bfloat16 lah = __float2bfloat16(la);
    __nv_bfloat16 lbh = __float2bfloat16(lb);
    lopack = ((uint32_t)__bfloat16_as_ushort(lbh) << 16) | (uint32_t)__bfloat16_as_ushort(lah);
    return ((uint32_t)__bfloat16_as_ushort(hb) << 16) | (uint32_t)__bfloat16_as_ushort(ha);
}
__device__ __forceinline__ float2 bf2_to_f2(uint32_t u) {
    __nv_bfloat162 b = *reinterpret_cast<__nv_bfloat162*>(&u);
    return __bfloat1622float2(b);
}

// ----------------------------- CSR construction ----------------------------
__global__ void k_zero_cnt() {
    int i = blockIdx.x * blockDim.x + threadIdx.x;
    if (i < Nn) g_cnt[i] = 0;
}
__global__ void k_hist(const int* __restrict__ dst) {
    int i = blockIdx.x * blockDim.x + threadIdx.x;
    if (i < Ee) atomicAdd(&g_cnt[dst[i]], 1);
}
__global__ void k_scan() {
    __shared__ int sums[1024];
    const int t = threadIdx.x;
    const int CH = 128;
    const int base = t * CH;
    int s = 0;
    for (int i = 0; i < CH; i++) {
        int idx = base + i;
        if (idx < Nn) s += g_cnt[idx];
    }
    sums[t] = s;
    __syncthreads();
    int mine = s;
    for (int d = 1; d < 1024; d <<= 1) {
        int v = (t >= d) ? sums[t - d] : 0;
        __syncthreads();
        sums[t] += v;
        __syncthreads();
    }
    int run = sums[t] - mine;
    for (int i = 0; i < CH; i++) {
        int idx = base + i;
        if (idx < Nn) {
            int c = g_cnt[idx];
            g_rowptr[idx] = run;
            g_cursor[idx] = run;
            g_invdeg[idx] = 1.0f / fmaxf((float)c, 1.0f);
            run += c;
        }
    }
    if (t == 0) g_rowptr[Nn] = Ee;
}
__global__ void k_fill(const int* __restrict__ src, const int* __restrict__ dst) {
    int i = blockIdx.x * blockDim.x + threadIdx.x;
    if (i < Ee) {
        int d = dst[i];
        int pos = atomicAdd(&g_cursor[d], 1);
        g_csr[pos] = src[i];
    }
}

// -------------- mean aggregation (warp / node, packed hi/lo) ---------------
__global__ __launch_bounds__(256) void k_agg(const uint2* __restrict__ hp) {
    int warp = (blockIdx.x * blockDim.x + threadIdx.x) >> 5;
    if (warp >= Nn) return;
    int lane = threadIdx.x & 31;
    int b = g_rowptr[warp];
    int e = g_rowptr[warp + 1];
    float a0 = 0.f, a1 = 0.f, a2 = 0.f, a3 = 0.f;
    int i = b;
    for (; i + 1 < e; i += 2) {
        int s0 = g_csr[i], s1 = g_csr[i + 1];
        uint4 u0 = *(const uint4*)(hp + (size_t)s0 * 64 + lane * 2);
        uint4 u1 = *(const uint4*)(hp + (size_t)s1 * 64 + lane * 2);
        float2 f;
        f = bf2_to_f2(u0.x); a0 += f.x; a1 += f.y;
        f = bf2_to_f2(u0.y); a0 += f.x; a1 += f.y;
        f = bf2_to_f2(u0.z); a2 += f.x; a3 += f.y;
        f = bf2_to_f2(u0.w); a2 += f.x; a3 += f.y;
        f = bf2_to_f2(u1.x); a0 += f.x; a1 += f.y;
        f = bf2_to_f2(u1.y); a0 += f.x; a1 += f.y;
        f = bf2_to_f2(u1.z); a2 += f.x; a3 += f.y;
        f = bf2_to_f2(u1.w); a2 += f.x; a3 += f.y;
    }
    if (i < e) {
        int s0 = g_csr[i];
        uint4 u0 = *(const uint4*)(hp + (size_t)s0 * 64 + lane * 2);
        float2 f;
        f = bf2_to_f2(u0.x); a0 += f.x; a1 += f.y;
        f = bf2_to_f2(u0.y); a0 += f.x; a1 += f.y;
        f = bf2_to_f2(u0.z); a2 += f.x; a3 += f.y;
        f = bf2_to_f2(u0.w); a2 += f.x; a3 += f.y;
    }
    float id = g_invdeg[warp];
    a0 *= id; a1 *= id; a2 *= id; a3 *= id;
    uint32_t lo0, lo1;
    uint32_t hi0 = pack_hilo(a0, a1, lo0);
    uint32_t hi1 = pack_hilo(a2, a3, lo1);
    uint4 o = make_uint4(hi0, lo0, hi1, lo1);
    *(uint4*)(g_mp + (size_t)warp * 64 + lane * 2) = o;
}

// ------------------------ conversions (weights, x) --------------------------
__global__ void k_wconv(const float* __restrict__ Wp, const float* __restrict__ Wl_h,
                        const float* __restrict__ Wr_h, const float* __restrict__ Wl_o,
                        const float* __restrict__ Wr_o) {
    int i = blockIdx.x * blockDim.x + threadIdx.x;
    if (i >= WTOT) return;
    float w;
    if (i < WOFF_H) {
        w = Wp[i];
    } else if (i < WOFF_O) {
        int j = i - WOFF_H;
        int layer = j / 32768;
        int r = j % 32768;
        int n = r >> 8, k = r & 255;
        w = (k < 128) ? Wl_h[layer * 16384 + n * 128 + k]
                      : Wr_h[layer * 16384 + n * 128 + (k - 128)];
    } else {
        int r = i - WOFF_O;
        int n = r >> 8, k = r & 255;
        w = (k < 128) ? Wl_o[n * 128 + k] : Wr_o[n * 128 + (k - 128)];
    }
    __nv_bfloat16 h = __float2bfloat16(w);
    g_Bhi[i] = h;
    g_Blo[i] = __float2bfloat16(w - __bfloat162float(h));
}

__global__ void k_xconv(const float* __restrict__ x) {
    int i = blockIdx.x * blockDim.x + threadIdx.x;  // float4 index
    if (i >= Nn * Hc / 4) return;
    float4 f = ((const float4*)x)[i];
    uint32_t lo0, lo1;
    uint32_t hi0 = pack_hilo(f.x, f.y, lo0);
    uint32_t hi1 = pack_hilo(f.z, f.w, lo1);
    ((uint4*)g_xp)[i] = make_uint4(hi0, lo0, hi1, lo1);
}

// ----------------------- mma.sync bf16x3 fused GEMM ------------------------
// out[m, :NOUT] = [A0|A1][m, :] @ W[:NOUT, :KTOT]^T + bias (+epilogue)
// A packed hi/lo (uint2 per channel pair). W bf16 hi/lo, staged per K-phase.
// 256 threads = 8 warps (2m x 4n); CTA tile m64 x nNOUT; warp m32 x n(NOUT/4).
template <int NOUT, bool TWO, bool RELU, bool RESID, bool PRE, bool WM, bool WPK>
__global__ __launch_bounds__(256, 2) void k_mgemm(
    const uint2* __restrict__ A0, const uint2* __restrict__ A1,
    const __nv_bfloat16* __restrict__ Bh, const __nv_bfloat16* __restrict__ Bl,
    const float* __restrict__ bias, const float* __restrict__ resid,
    float* __restrict__ outm, float* __restrict__ outp, uint2* __restrict__ outpk) {
    extern __shared__ char smem[];
    constexpr int KTOT = TWO ? 256 : 128;
    constexpr int AST = 136;                    // bf16 smem row stride per phase
    constexpr int OFF_BH = 0;
    constexpr int OFF_BL = NOUT * AST * 2;
    constexpr int OFF_BIAS = 2 * NOUT * AST * 2;
    constexpr int NI = NOUT / 32;               // n8 tiles per warp (4 or 2)
    constexpr int NW = NI * 8;                  // warp n width (32 or 16)

    const uint32_t sm32 = smem_to_u32(smem);
    const int tid = threadIdx.x;
    const int lane = tid & 31;
    const int wid = tid >> 5;
    const int wm = wid & 1;       // m block (32 rows)
    const int wn = wid >> 1;      // n block (NW cols)
    const int m0 = blockIdx.x * 64;

    if (tid < NOUT) *(float*)(smem + OFF_BIAS + tid * 4) = bias[tid];

    // ldmatrix lane address for B (16x16 tile per x4)
    const int r8 = lane & 7, q = lane >> 3;
    const uint32_t boff =
        (uint32_t)(((wn * NW) + (q >> 1) * 8 + r8) * AST + (q & 1) * 8) * 2;

    const int q4 = lane & 3;
    const int rbase = m0 + wm * 32 + (lane >> 2);

    float acc[2][NI][4];
#pragma unroll
    for (int mi = 0; mi < 2; mi++)
#pragma unroll
        for (int ni = 0; ni < NI; ni++)
#pragma unroll
            for (int c = 0; c < 4; c++) acc[mi][ni][c] = 0.f;

#pragma unroll
    for (int p = 0; p < (TWO ? 2 : 1); p++) {
        if (p) __syncthreads();
        // ---- stage B phase p (hi & lo) ----
        {
            constexpr int NG = NOUT * 16;        // 16B granules
            const int kofs = p * 128;
            for (int g = tid; g < NG; g += 256) {
                int n = g >> 4;
                int kc = (g & 15) * 8;
                *(uint4*)(smem + OFF_BH + ((size_t)n * AST + kc) * 2) =
                    *(const uint4*)(Bh + (size_t)n * KTOT + kofs + kc);
                *(uint4*)(smem + OFF_BL + ((size_t)n * AST + kc) * 2) =
                    *(const uint4*)(Bl + (size_t)n * KTOT + kofs + kc);
            }
        }
        __syncthreads();

        const uint2* __restrict__ Ap = p ? A1 : A0;
        const uint2* a0p = Ap + (size_t)(rbase)*64 + q4;
        const uint2* a1p = Ap + (size_t)(rbase + 8) * 64 + q4;
        const uint2* a2p = Ap + (size_t)(rbase + 16) * 64 + q4;
        const uint2* a3p = Ap + (size_t)(rbase + 24) * 64 + q4;

#pragma unroll
        for (int k8 = 0; k8 < 8; k8++) {
            // ---- A fragments: one LDG.64 delivers {hi2, lo2} ----
            uint2 u00 = a0p[k8 * 8],     u01 = a0p[k8 * 8 + 4];
            uint2 u10 = a1p[k8 * 8],     u11 = a1p[k8 * 8 + 4];
            uint2 u20 = a2p[k8 * 8],     u21 = a2p[k8 * 8 + 4];
            uint2 u30 = a3p[k8 * 8],     u31 = a3p[k8 * 8 + 4];
            uint32_t ah[2][4] = {{u00.x, u10.x, u01.x, u11.x},
                                 {u20.x, u30.x, u21.x, u31.x}};
            uint32_t al[2][4] = {{u00.y, u10.y, u01.y, u11.y},
                                 {u20.y, u30.y, u21.y, u31.y}};
            // ---- B hi fragments + 2 passes ----
            uint32_t bh[NI / 2][4];
#pragma unroll
            for (int nt = 0; nt < NI / 2; nt++)
                ldsm_x4(bh[nt], sm32 + OFF_BH + boff + nt * 16 * AST * 2 + k8 * 32);
#pragma unroll
            for (int mi = 0; mi < 2; mi++)
#pragma unroll
                for (int ni = 0; ni < NI; ni++)
                    mma_bf16(acc[mi][ni], ah[mi], &bh[ni >> 1][(ni & 1) * 2]);
#pragma unroll
            for (int mi = 0; mi < 2; mi++)
#pragma unroll
                for (int ni = 0; ni < NI; ni++)
                    mma_bf16(acc[mi][ni], al[mi], &bh[ni >> 1][(ni & 1) * 2]);
            // ---- B lo fragments + 1 pass ----
            uint32_t bl[NI / 2][4];
#pragma unroll
            for (int nt = 0; nt < NI / 2; nt++)
                ldsm_x4(bl[nt], sm32 + OFF_BL + boff + nt * 16 * AST * 2 + k8 * 32);
#pragma unroll
            for (int mi = 0; mi < 2; mi++)
#pragma unroll
                for (int ni = 0; ni < NI; ni++)
                    mma_bf16(acc[mi][ni], ah[mi], &bl[ni >> 1][(ni & 1) * 2]);
        }
    }

    // ------------------------------ epilogue -------------------------------
    const float* biasS = (const float*)(smem + OFF_BIAS);
#pragma unroll
    for (int mi = 0; mi < 2; mi++) {
#pragma unroll
        for (int ni = 0; ni < NI; ni++) {
            const int col = wn * NW + ni * 8 + q4 * 2;
            const float b0 = biasS[col], b1 = biasS[col + 1];
#pragma unroll
            for (int half = 0; half < 2; half++) {
                const int row = rbase + mi * 16 + half * 8;
                float x0 = acc[mi][ni][half * 2 + 0] + b0;
                float x1 = acc[mi][ni][half * 2 + 1] + b1;
                const size_t off = (size_t)row * NOUT + col;
                if (PRE) *(float2*)(outp + off) = make_float2(x0, x1);
                if (RELU) { x0 = fmaxf(x0, 0.f); x1 = fmaxf(x1, 0.f); }
                if (RESID) {
                    float2 rr = *(const float2*)(resid + off);
                    x0 = fmaf(0.2f, rr.x, x0);
                    x1 = fmaf(0.2f, rr.y, x1);
                }
                if (WM) {
                    if (row < Nn) *(float2*)(outm + off) = make_float2(x0, x1);
                }
                if (WPK) {
                    uint32_t lo;
                    uint32_t hi = pack_hilo(x0, x1, lo);
                    outpk[(size_t)row * 64 + (col >> 1)] = make_uint2(hi, lo);
                }
            }
        }
    }
}

// ------------------------------ log-softmax --------------------------------
__global__ __launch_bounds__(256) void k_lsm(float* __restrict__ out) {
    int warp = (blockIdx.x * blockDim.x + threadIdx.x) >> 5;
    if (warp >= Nn) return;
    int lane = threadIdx.x & 31;
    float2 v = *(float2*)(out + (size_t)warp * Oc + lane * 2);
    float m = fmaxf(v.x, v.y);
#pragma unroll
    for (int o = 16; o; o >>= 1) m = fmaxf(m, __shfl_xor_sync(0xFFFFFFFFu, m, o));
    float s = expf(v.x - m) + expf(v.y - m);
#pragma unroll
    for (int o = 16; o; o >>= 1) s += __shfl_xor_sync(0xFFFFFFFFu, s, o);
    float l = m + logf(s);
    v.x -= l;
    v.y -= l;
    *(float2*)(out + (size_t)warp * Oc + lane * 2) = v;
}

// ------------------------------- launcher ----------------------------------
extern "C" void kernel_launch(void* const* d_in, const int* in_sizes, int n_in,
                              void* d_out, int out_size) {
    const float* x    = (const float*)d_in[0];
    const int*   ei   = (const int*)d_in[1];
    const float* Wp   = (const float*)d_in[2];
    const float* bp   = (const float*)d_in[3];
    const float* Wl_h = (const float*)d_in[4];
    const float* bl_h = (const float*)d_in[5];
    const float* Wr_h = (const float*)d_in[6];
    const float* Wl_o = (const float*)d_in[7];
    const float* bl_o = (const float*)d_in[8];
    const float* Wr_o = (const float*)d_in[9];
    const int* src = ei;
    const int* dst = ei + Ee;
    float* out = (float*)d_out;

    float* p_inp;
    cudaGetSymbolAddress((void**)&p_inp, g_inp);
    uint2 *p_xp, *p_hp0, *p_hp1, *p_mp;
    cudaGetSymbolAddress((void**)&p_xp, g_xp);
    cudaGetSymbolAddress((void**)&p_hp0, g_hp0);
    cudaGetSymbolAddress((void**)&p_hp1, g_hp1);
    cudaGetSymbolAddress((void**)&p_mp, g_mp);
    __nv_bfloat16 *p_bhi, *p_blo;
    cudaGetSymbolAddress((void**)&p_bhi, g_Bhi);
    cudaGetSymbolAddress((void**)&p_blo, g_Blo);

    auto gemm_in  = k_mgemm<128, false, true, false, true, false, true>;
    auto gemm_hid = k_mgemm<128, true, true, true, false, false, true>;
    auto gemm_out = k_mgemm<64, true, false, false, false, true, false>;
    const int SM_H = 2 * 128 * 136 * 2 + 512;  // 70144
    const int SM_O = 2 * 64 * 136 * 2 + 256;   // 35072
    cudaFuncSetAttribute(gemm_in, cudaFuncAttributeMaxDynamicSharedMemorySize, SM_H);
    cudaFuncSetAttribute(gemm_hid, cudaFuncAttributeMaxDynamicSharedMemorySize, SM_H);
    cudaFuncSetAttribute(gemm_out, cudaFuncAttributeMaxDynamicSharedMemorySize, SM_O);

    // Launch order: ncu captures launch index 3 -> gemm_in.
    k_wconv<<<(WTOT + 255) / 256, 256>>>(Wp, Wl_h, Wr_h, Wl_o, Wr_o);          // 0
    k_xconv<<<(Nn * Hc / 4 + 255) / 256, 256>>>(x);                            // 1
    k_zero_cnt<<<(Nn + 255) / 256, 256>>>();                                   // 2
    gemm_in<<<NT2, 256, SM_H>>>(p_xp, nullptr, p_bhi + WOFF_IN, p_blo + WOFF_IN,  // 3
                                bp, nullptr, nullptr, p_inp, p_hp0);
    k_hist<<<(Ee + 255) / 256, 256>>>(dst);                                    // 4
    k_scan<<<1, 1024>>>();                                                     // 5
    k_fill<<<(Ee + 255) / 256, 256>>>(src, dst);                               // 6

    const int ga = ((Nn * 32) + 255) / 256;

    uint2 *hp = p_hp0, *np = p_hp1;
    for (int i = 0; i < 3; i++) {
        k_agg<<<ga, 256>>>(hp);
        gemm_hid<<<NT2, 256, SM_H>>>(p_mp, hp,
                                     p_bhi + WOFF_H + i * 32768, p_blo + WOFF_H + i * 32768,
                                     bl_h + (size_t)i * 128, p_inp,
                                     nullptr, nullptr, np);
        uint2* t = hp; hp = np; np = t;
    }

    k_agg<<<ga, 256>>>(hp);
    gemm_out<<<NT2, 256, SM_O>>>(p_mp, hp, p_bhi + WOFF_O, p_blo + WOFF_O,
                                 bl_o, nullptr, out, nullptr, nullptr);
    k_lsm<<<ga, 256>>>(out);
}

// round 7
// speedup vs baseline: 1.1226x; 1.0233x over previous
#include <cuda_runtime.h>
#include <cuda_bf16.h>
#include <cstdint>

// ---------------------------------------------------------------------------
// GraphSAGE forward on GB300 — smem-fed mma.sync bf16x3 GEMMs (cp.async
// staging, ldmatrix A+B) over block-packed hi/lo activations + CSR mean agg.
// Activation row layout (128 cols, 512B): 8 k-blocks x [32B hi | 32B lo].
// ---------------------------------------------------------------------------
namespace {
constexpr int Nn = 100000;   // nodes
constexpr int Ee = 1600000;  // edges
constexpr int Hc = 128;      // hidden channels
constexpr int Oc = 64;       // out channels
constexpr int NP = 100096;   // padded rows (multiple of 128)
constexpr int NT = NP / 128; // 782 CTA tiles
// weight scratch layout (combined [Wl|Wr] per layer, row-major [n][k])
constexpr int WOFF_IN = 0;
constexpr int WOFF_H = 16384;
constexpr int WOFF_O = 16384 + 3 * 32768;
constexpr int WTOT = WOFF_O + 64 * 256;  // 131072
}

// ------------------------- static device scratch ---------------------------
__device__ float g_inp[(size_t)NP * Hc];   // pre-relu inProj (residual)
__device__ uint4 g_xp[(size_t)NP * 32];    // x packed (block hi/lo)
__device__ uint4 g_hp0[(size_t)NP * 32];   // h packed ping
__device__ uint4 g_hp1[(size_t)NP * 32];   // h packed pong
__device__ uint4 g_mp[(size_t)NP * 32];    // mean packed
__device__ float g_invdeg[Nn];
__device__ int   g_cnt[Nn];
__device__ int   g_rowptr[Nn + 1];
__device__ int   g_cursor[Nn];
__device__ int   g_csr[Ee];
__device__ __align__(16) __nv_bfloat16 g_Bhi[WTOT];
__device__ __align__(16) __nv_bfloat16 g_Blo[WTOT];

// ------------------------------ PTX helpers --------------------------------
__device__ __forceinline__ uint32_t smem_to_u32(const void* p) {
    uint32_t a;
    asm("{ .reg .u64 t; cvta.to.shared.u64 t, %1; cvt.u32.u64 %0, t; }"
        : "=r"(a) : "l"(p));
    return a;
}
__device__ __forceinline__ void ldsm_x4(uint32_t* r, uint32_t addr) {
    asm volatile("ldmatrix.sync.aligned.m8n8.x4.shared.b16 {%0,%1,%2,%3}, [%4];"
                 : "=r"(r[0]), "=r"(r[1]), "=r"(r[2]), "=r"(r[3]) : "r"(addr));
}
__device__ __forceinline__ void mma_bf16(float* c, const uint32_t* a, const uint32_t* b) {
    asm volatile(
        "mma.sync.aligned.m16n8k16.row.col.f32.bf16.bf16.f32 "
        "{%0,%1,%2,%3}, {%4,%5,%6,%7}, {%8,%9}, {%0,%1,%2,%3};"
        : "+f"(c[0]), "+f"(c[1]), "+f"(c[2]), "+f"(c[3])
        : "r"(a[0]), "r"(a[1]), "r"(a[2]), "r"(a[3]), "r"(b[0]), "r"(b[1]));
}
__device__ __forceinline__ void cp16(uint32_t saddr, const void* g) {
    asm volatile("cp.async.cg.shared.global [%0], [%1], 16;"
                 :: "r"(saddr), "l"(g) : "memory");
}
#define CP_COMMIT() asm volatile("cp.async.commit_group;" ::: "memory")
#define CP_WAIT0()  asm volatile("cp.async.wait_group 0;" ::: "memory")

__device__ __forceinline__ uint32_t pack_hilo(float a, float b, uint32_t& lopack) {
    __nv_bfloat16 ha = __float2bfloat16(a);
    __nv_bfloat16 hb = __float2bfloat16(b);
    float la = a - __bfloat162float(ha);
    float lb = b - __bfloat162float(hb);
    __nv_bfloat16 lah = __float2bfloat16(la);
    __nv_bfloat16 lbh = __float2bfloat16(lb);
    lopack = ((uint32_t)__bfloat16_as_ushort(lbh) << 16) | (uint32_t)__bfloat16_as_ushort(lah);
    return ((uint32_t)__bfloat16_as_ushort(hb) << 16) | (uint32_t)__bfloat16_as_ushort(ha);
}
__device__ __forceinline__ float2 bf2_to_f2(uint32_t u) {
    __nv_bfloat162 b = *reinterpret_cast<__nv_bfloat162*>(&u);
    return __bfloat1622float2(b);
}

// ----------------------------- CSR construction ----------------------------
__global__ void k_zero_cnt() {
    int i = blockIdx.x * blockDim.x + threadIdx.x;
    if (i < Nn) g_cnt[i] = 0;
}
__global__ void k_hist(const int* __restrict__ dst) {
    int i = blockIdx.x * blockDim.x + threadIdx.x;
    if (i < Ee) atomicAdd(&g_cnt[dst[i]], 1);
}
__global__ void k_scan() {
    __shared__ int sums[1024];
    const int t = threadIdx.x;
    const int CH = 128;
    const int base = t * CH;
    int s = 0;
    for (int i = 0; i < CH; i++) {
        int idx = base + i;
        if (idx < Nn) s += g_cnt[idx];
    }
    sums[t] = s;
    __syncthreads();
    int mine = s;
    for (int d = 1; d < 1024; d <<= 1) {
        int v = (t >= d) ? sums[t - d] : 0;
        __syncthreads();
        sums[t] += v;
        __syncthreads();
    }
    int run = sums[t] - mine;
    for (int i = 0; i < CH; i++) {
        int idx = base + i;
        if (idx < Nn) {
            int c = g_cnt[idx];
            g_rowptr[idx] = run;
            g_cursor[idx] = run;
            g_invdeg[idx] = 1.0f / fmaxf((float)c, 1.0f);
            run += c;
        }
    }
    if (t == 0) g_rowptr[Nn] = Ee;
}
__global__ void k_fill(const int* __restrict__ src, const int* __restrict__ dst) {
    int i = blockIdx.x * blockDim.x + threadIdx.x;
    if (i < Ee) {
        int d = dst[i];
        int pos = atomicAdd(&g_cursor[d], 1);
        g_csr[pos] = src[i];
    }
}

// -------------- mean aggregation (warp / node, block-packed) ---------------
// lane l: block b = l>>2, quarter q4 = l&3. q4 0/1 = hi cols (+0..7 / +8..15),
// q4 2/3 = lo of same cols. shfl_xor(2) combines hi+lo into full fp32 sums.
__global__ __launch_bounds__(256) void k_agg(const uint4* __restrict__ hp) {
    int warp = (blockIdx.x * blockDim.x + threadIdx.x) >> 5;
    if (warp >= Nn) return;
    int lane = threadIdx.x & 31;
    int b = g_rowptr[warp];
    int e = g_rowptr[warp + 1];
    float a0 = 0.f, a1 = 0.f, a2 = 0.f, a3 = 0.f;
    float a4 = 0.f, a5 = 0.f, a6 = 0.f, a7 = 0.f;
    int i = b;
    for (; i + 1 < e; i += 2) {
        int s0 = g_csr[i], s1 = g_csr[i + 1];
        uint4 u0 = hp[(size_t)s0 * 32 + lane];
        uint4 u1 = hp[(size_t)s1 * 32 + lane];
        float2 f;
        f = bf2_to_f2(u0.x); a0 += f.x; a1 += f.y;
        f = bf2_to_f2(u0.y); a2 += f.x; a3 += f.y;
        f = bf2_to_f2(u0.z); a4 += f.x; a5 += f.y;
        f = bf2_to_f2(u0.w); a6 += f.x; a7 += f.y;
        f = bf2_to_f2(u1.x); a0 += f.x; a1 += f.y;
        f = bf2_to_f2(u1.y); a2 += f.x; a3 += f.y;
        f = bf2_to_f2(u1.z); a4 += f.x; a5 += f.y;
        f = bf2_to_f2(u1.w); a6 += f.x; a7 += f.y;
    }
    if (i < e) {
        int s0 = g_csr[i];
        uint4 u0 = hp[(size_t)s0 * 32 + lane];
        float2 f;
        f = bf2_to_f2(u0.x); a0 += f.x; a1 += f.y;
        f = bf2_to_f2(u0.y); a2 += f.x; a3 += f.y;
        f = bf2_to_f2(u0.z); a4 += f.x; a5 += f.y;
        f = bf2_to_f2(u0.w); a6 += f.x; a7 += f.y;
    }
    // combine hi-plane and lo-plane partial sums (partner lane = lane^2)
    a0 += __shfl_xor_sync(0xFFFFFFFFu, a0, 2);
    a1 += __shfl_xor_sync(0xFFFFFFFFu, a1, 2);
    a2 += __shfl_xor_sync(0xFFFFFFFFu, a2, 2);
    a3 += __shfl_xor_sync(0xFFFFFFFFu, a3, 2);
    a4 += __shfl_xor_sync(0xFFFFFFFFu, a4, 2);
    a5 += __shfl_xor_sync(0xFFFFFFFFu, a5, 2);
    a6 += __shfl_xor_sync(0xFFFFFFFFu, a6, 2);
    a7 += __shfl_xor_sync(0xFFFFFFFFu, a7, 2);
    float id = g_invdeg[warp];
    a0 *= id; a1 *= id; a2 *= id; a3 *= id;
    a4 *= id; a5 *= id; a6 *= id; a7 *= id;
    const bool hiHalf = (lane & 2) == 0;
    uint32_t o[4], lo;
    uint32_t hi;
    hi = pack_hilo(a0, a1, lo); o[0] = hiHalf ? hi : lo;
    hi = pack_hilo(a2, a3, lo); o[1] = hiHalf ? hi : lo;
    hi = pack_hilo(a4, a5, lo); o[2] = hiHalf ? hi : lo;
    hi = pack_hilo(a6, a7, lo); o[3] = hiHalf ? hi : lo;
    g_mp[(size_t)warp * 32 + lane] = make_uint4(o[0], o[1], o[2], o[3]);
}

// ------------------------ conversions (weights, x) --------------------------
__global__ void k_wconv(const float* __restrict__ Wp, const float* __restrict__ Wl_h,
                        const float* __restrict__ Wr_h, const float* __restrict__ Wl_o,
                        const float* __restrict__ Wr_o) {
    int i = blockIdx.x * blockDim.x + threadIdx.x;
    if (i >= WTOT) return;
    float w;
    if (i < WOFF_H) {
        w = Wp[i];
    } else if (i < WOFF_O) {
        int j = i - WOFF_H;
        int layer = j / 32768;
        int r = j % 32768;
        int n = r >> 8, k = r & 255;
        w = (k < 128) ? Wl_h[layer * 16384 + n * 128 + k]
                      : Wr_h[layer * 16384 + n * 128 + (k - 128)];
    } else {
        int r = i - WOFF_O;
        int n = r >> 8, k = r & 255;
        w = (k < 128) ? Wl_o[n * 128 + k] : Wr_o[n * 128 + (k - 128)];
    }
    __nv_bfloat16 h = __float2bfloat16(w);
    g_Bhi[i] = h;
    g_Blo[i] = __float2bfloat16(w - __bfloat162float(h));
}

// x -> block-packed hi/lo; thread per 4 cols
__global__ void k_xconv(const float* __restrict__ x) {
    int i = blockIdx.x * blockDim.x + threadIdx.x;
    if (i >= Nn * 32) return;
    int row = i >> 5, g = i & 31;
    int blk = g >> 2, quad = g & 3;
    const float4 f = *(const float4*)(x + (size_t)row * 128 + g * 4);
    uint32_t lo0, lo1;
    uint32_t hi0 = pack_hilo(f.x, f.y, lo0);
    uint32_t hi1 = pack_hilo(f.z, f.w, lo1);
    char* rb = (char*)g_xp + (size_t)row * 512 + blk * 64 + quad * 8;
    *(uint2*)rb = make_uint2(hi0, hi1);
    *(uint2*)(rb + 32) = make_uint2(lo0, lo1);
}

// ----------------------- smem-fed mma.sync bf16x3 GEMM ---------------------
// CTA: m128 x nNOUT. 256 threads = 8 warps (4m x 2n), warp m32 x n(NOUT/2).
// A: block-packed activations staged whole-phase via cp.async (L1 bypass).
// B: bf16 hi/lo weights staged per phase. All mma operands via ldmatrix.
template <int NOUT, int NPH, bool RELU, bool RESID, bool PRE, bool WM, bool WPK>
__global__ __launch_bounds__(256, 1) void k_mgemm(
    const uint4* __restrict__ A0, const uint4* __restrict__ A1,
    const __nv_bfloat16* __restrict__ Bh, const __nv_bfloat16* __restrict__ Bl,
    const float* __restrict__ bias, const float* __restrict__ resid,
    float* __restrict__ outm, float* __restrict__ outp, uint4* __restrict__ outpk) {
    extern __shared__ char smem[];
    constexpr int ASZ = 128 * 528;           // A plane (rows pitch 528B)
    constexpr int OFF_B = NPH * ASZ;
    constexpr int BPL = NOUT * 272;          // B plane (rows pitch 272B)
    constexpr int OFF_BIAS = OFF_B + 2 * BPL;
    constexpr int KTOT = NPH * 128;
    constexpr int NI = NOUT / 16;            // n8 tiles per warp (8 or 4)
    constexpr int NW = NI * 8;

    const uint32_t sm32 = smem_to_u32(smem);
    const int tid = threadIdx.x;
    const int lane = tid & 31;
    const int wid = tid >> 5;
    const int wm = wid & 3;
    const int wn = wid >> 2;
    const int m0 = blockIdx.x * 128;

    // ---- stage all A phases + B phase 0 ----
#pragma unroll
    for (int p = 0; p < NPH; p++) {
        const uint4* Ap = (p ? A1 : A0) + (size_t)m0 * 32;
        for (int g = tid; g < 4096; g += 256) {
            int r = g >> 5, c = g & 31;
            cp16(sm32 + p * ASZ + r * 528 + c * 16, Ap + r * 32 + c);
        }
    }
    for (int g = tid; g < NOUT * 16; g += 256) {
        int n = g >> 4, c = g & 15;
        cp16(sm32 + OFF_B + n * 272 + c * 16, Bh + (size_t)n * KTOT + c * 8);
        cp16(sm32 + OFF_B + BPL + n * 272 + c * 16, Bl + (size_t)n * KTOT + c * 8);
    }
    CP_COMMIT();
    if (tid < NOUT) *(float*)(smem + OFF_BIAS + tid * 4) = bias[tid];
    CP_WAIT0();
    __syncthreads();

    const int r8 = lane & 7, q = lane >> 3;
    // A ldmatrix lane addr: rows wm*32 + (q&1)*8 + r8, k-half (q>>1)
    const uint32_t aoff =
        (uint32_t)((wm * 32 + (q & 1) * 8 + r8) * 528 + (q >> 1) * 16);
    // B ldmatrix lane addr
    const uint32_t boff =
        (uint32_t)((wn * NW + (q >> 1) * 8 + r8) * 272 + (q & 1) * 16);
    const uint32_t bBaseH = sm32 + OFF_B + boff;
    const uint32_t bBaseL = bBaseH + BPL;

    float acc[2][NI][4];
#pragma unroll
    for (int mi = 0; mi < 2; mi++)
#pragma unroll
        for (int ni = 0; ni < NI; ni++)
#pragma unroll
            for (int c = 0; c < 4; c++) acc[mi][ni][c] = 0.f;

#pragma unroll
    for (int p = 0; p < NPH; p++) {
        if (p > 0) {
            __syncthreads();
            for (int g = tid; g < NOUT * 16; g += 256) {
                int n = g >> 4, c = g & 15;
                cp16(sm32 + OFF_B + n * 272 + c * 16,
                     Bh + (size_t)n * KTOT + p * 128 + c * 8);
                cp16(sm32 + OFF_B + BPL + n * 272 + c * 16,
                     Bl + (size_t)n * KTOT + p * 128 + c * 8);
            }
            CP_COMMIT();
            CP_WAIT0();
            __syncthreads();
        }
        const uint32_t aBase = sm32 + (uint32_t)(p * ASZ) + aoff;
#pragma unroll
        for (int kb = 0; kb < 8; kb++) {
            uint32_t ah0[4], al0[4], ah1[4], al1[4];
            ldsm_x4(ah0, aBase + kb * 64);
            ldsm_x4(al0, aBase + kb * 64 + 32);
            ldsm_x4(ah1, aBase + 16 * 528 + kb * 64);
            ldsm_x4(al1, aBase + 16 * 528 + kb * 64 + 32);
            uint32_t bhf[NI / 2][4], blf[NI / 2][4];
#pragma unroll
            for (int nt = 0; nt < NI / 2; nt++) {
                ldsm_x4(bhf[nt], bBaseH + nt * 16 * 272 + kb * 32);
                ldsm_x4(blf[nt], bBaseL + nt * 16 * 272 + kb * 32);
            }
#pragma unroll
            for (int ni = 0; ni < NI; ni++) {
                mma_bf16(acc[0][ni], ah0, &bhf[ni >> 1][(ni & 1) * 2]);
                mma_bf16(acc[1][ni], ah1, &bhf[ni >> 1][(ni & 1) * 2]);
            }
#pragma unroll
            for (int ni = 0; ni < NI; ni++) {
                mma_bf16(acc[0][ni], al0, &bhf[ni >> 1][(ni & 1) * 2]);
                mma_bf16(acc[1][ni], al1, &bhf[ni >> 1][(ni & 1) * 2]);
            }
#pragma unroll
            for (int ni = 0; ni < NI; ni++) {
                mma_bf16(acc[0][ni], ah0, &blf[ni >> 1][(ni & 1) * 2]);
                mma_bf16(acc[1][ni], ah1, &blf[ni >> 1][(ni & 1) * 2]);
            }
        }
    }

    // ------------------------------ epilogue -------------------------------
    const float* biasS = (const float*)(smem + OFF_BIAS);
    const int q4 = lane & 3;
    const int rbase = m0 + wm * 32 + (lane >> 2);
#pragma unroll
    for (int mi = 0; mi < 2; mi++) {
#pragma unroll
        for (int ni = 0; ni < NI; ni++) {
            const int col = wn * NW + ni * 8 + q4 * 2;
            const float b0 = biasS[col], b1 = biasS[col + 1];
#pragma unroll
            for (int half = 0; half < 2; half++) {
                const int row = rbase + mi * 16 + half * 8;
                float x0 = acc[mi][ni][half * 2 + 0] + b0;
                float x1 = acc[mi][ni][half * 2 + 1] + b1;
                if (PRE) *(float2*)(outp + (size_t)row * 128 + col) = make_float2(x0, x1);
                if (RELU) { x0 = fmaxf(x0, 0.f); x1 = fmaxf(x1, 0.f); }
                if (RESID) {
                    float2 rr = *(const float2*)(resid + (size_t)row * 128 + col);
                    x0 = fmaf(0.2f, rr.x, x0);
                    x1 = fmaf(0.2f, rr.y, x1);
                }
                if (WM) {
                    if (row < Nn)
                        *(float2*)(outm + (size_t)row * NOUT + col) = make_float2(x0, x1);
                }
                if (WPK) {
                    char* rb = (char*)outpk + (size_t)row * 512 + (col >> 4) * 64 +
                               (col & 15) * 2;
                    uint32_t lo;
                    uint32_t hi = pack_hilo(x0, x1, lo);
                    *(uint32_t*)rb = hi;
                    *(uint32_t*)(rb + 32) = lo;
                }
            }
        }
    }
}

// ------------------------------ log-softmax --------------------------------
__global__ __launch_bounds__(256) void k_lsm(float* __restrict__ out) {
    int warp = (blockIdx.x * blockDim.x + threadIdx.x) >> 5;
    if (warp >= Nn) return;
    int lane = threadIdx.x & 31;
    float2 v = *(float2*)(out + (size_t)warp * Oc + lane * 2);
    float m = fmaxf(v.x, v.y);
#pragma unroll
    for (int o = 16; o; o >>= 1) m = fmaxf(m, __shfl_xor_sync(0xFFFFFFFFu, m, o));
    float s = expf(v.x - m) + expf(v.y - m);
#pragma unroll
    for (int o = 16; o; o >>= 1) s += __shfl_xor_sync(0xFFFFFFFFu, s, o);
    float l = m + logf(s);
    v.x -= l;
    v.y -= l;
    *(float2*)(out + (size_t)warp * Oc + lane * 2) = v;
}

// ------------------------------- launcher ----------------------------------
extern "C" void kernel_launch(void* const* d_in, const int* in_sizes, int n_in,
                              void* d_out, int out_size) {
    const float* x    = (const float*)d_in[0];
    const int*   ei   = (const int*)d_in[1];
    const float* Wp   = (const float*)d_in[2];
    const float* bp   = (const float*)d_in[3];
    const float* Wl_h = (const float*)d_in[4];
    const float* bl_h = (const float*)d_in[5];
    const float* Wr_h = (const float*)d_in[6];
    const float* Wl_o = (const float*)d_in[7];
    const float* bl_o = (const float*)d_in[8];
    const float* Wr_o = (const float*)d_in[9];
    const int* src = ei;
    const int* dst = ei + Ee;
    float* out = (float*)d_out;

    float* p_inp;
    cudaGetSymbolAddress((void**)&p_inp, g_inp);
    uint4 *p_xp, *p_hp0, *p_hp1, *p_mp;
    cudaGetSymbolAddress((void**)&p_xp, g_xp);
    cudaGetSymbolAddress((void**)&p_hp0, g_hp0);
    cudaGetSymbolAddress((void**)&p_hp1, g_hp1);
    cudaGetSymbolAddress((void**)&p_mp, g_mp);
    __nv_bfloat16 *p_bhi, *p_blo;
    cudaGetSymbolAddress((void**)&p_bhi, g_Bhi);
    cudaGetSymbolAddress((void**)&p_blo, g_Blo);

    auto gemm_in  = k_mgemm<128, 1, true, false, true, false, true>;
    auto gemm_hid = k_mgemm<128, 2, true, true, false, false, true>;
    auto gemm_out = k_mgemm<64, 2, false, false, false, true, false>;
    const int SM_IN  = 1 * 128 * 528 + 2 * 128 * 272 + 512;  // 137728
    const int SM_HID = 2 * 128 * 528 + 2 * 128 * 272 + 512;  // 205312
    const int SM_OUT = 2 * 128 * 528 + 2 * 64 * 272 + 256;   // 170240
    cudaFuncSetAttribute(gemm_in, cudaFuncAttributeMaxDynamicSharedMemorySize, SM_IN);
    cudaFuncSetAttribute(gemm_hid, cudaFuncAttributeMaxDynamicSharedMemorySize, SM_HID);
    cudaFuncSetAttribute(gemm_out, cudaFuncAttributeMaxDynamicSharedMemorySize, SM_OUT);

    // Launch order: ncu captures launch index 3 -> gemm_in.
    k_wconv<<<(WTOT + 255) / 256, 256>>>(Wp, Wl_h, Wr_h, Wl_o, Wr_o);          // 0
    k_xconv<<<(Nn * 32 + 255) / 256, 256>>>(x);                                // 1
    k_zero_cnt<<<(Nn + 255) / 256, 256>>>();                                   // 2
    gemm_in<<<NT, 256, SM_IN>>>(p_xp, nullptr, p_bhi + WOFF_IN, p_blo + WOFF_IN,  // 3
                                bp, nullptr, nullptr, p_inp, p_hp0);
    k_hist<<<(Ee + 255) / 256, 256>>>(dst);                                    // 4
    k_scan<<<1, 1024>>>();                                                     // 5
    k_fill<<<(Ee + 255) / 256, 256>>>(src, dst);                               // 6

    const int ga = ((Nn * 32) + 255) / 256;

    uint4 *hp = p_hp0, *np = p_hp1;
    for (int i = 0; i < 3; i++) {
        k_agg<<<ga, 256>>>(hp);
        gemm_hid<<<NT, 256, SM_HID>>>(p_mp, hp,
                                      p_bhi + WOFF_H + i * 32768, p_blo + WOFF_H + i * 32768,
                                      bl_h + (size_t)i * 128, p_inp,
                                      nullptr, nullptr, np);
        uint4* t = hp; hp = np; np = t;
    }

    k_agg<<<ga, 256>>>(hp);
    gemm_out<<<NT, 256, SM_OUT>>>(p_mp, hp, p_bhi + WOFF_O, p_blo + WOFF_O,
                                  bl_o, nullptr, out, nullptr, nullptr);
    k_lsm<<<ga, 256>>>(out);
}

// round 8
// speedup vs baseline: 1.1982x; 1.0674x over previous
#include <cuda_runtime.h>
#include <cuda_bf16.h>
#include <cstdint>

// ---------------------------------------------------------------------------
// GraphSAGE forward on GB300 — smem-fed mma.sync bf16x3 GEMMs (512 thr,
// 16 warps) + hi-plane CSR mean aggregation over block-packed activations.
// Activation row layout (128 cols, 512B): 8 k-blocks x [32B hi | 32B lo].
// ---------------------------------------------------------------------------
namespace {
constexpr int Nn = 100000;   // nodes
constexpr int Ee = 1600000;  // edges
constexpr int Hc = 128;      // hidden channels
constexpr int Oc = 64;       // out channels
constexpr int NP = 100096;   // padded rows (multiple of 128)
constexpr int NT = NP / 128; // 782 CTA tiles
// weight scratch layout (combined [Wl|Wr] per layer, row-major [n][k])
constexpr int WOFF_IN = 0;
constexpr int WOFF_H = 16384;
constexpr int WOFF_O = 16384 + 3 * 32768;
constexpr int WTOT = WOFF_O + 64 * 256;  // 131072
}

// ------------------------- static device scratch ---------------------------
__device__ float g_inp[(size_t)NP * Hc];   // pre-relu inProj (residual)
__device__ uint4 g_xp[(size_t)NP * 32];    // x packed (block hi/lo)
__device__ uint4 g_hp0[(size_t)NP * 32];   // h packed ping
__device__ uint4 g_hp1[(size_t)NP * 32];   // h packed pong
__device__ uint4 g_mp[(size_t)NP * 32];    // mean packed
__device__ float g_invdeg[Nn];
__device__ int   g_cnt[Nn];
__device__ int   g_rowptr[Nn + 1];
__device__ int   g_cursor[Nn];
__device__ int   g_csr[Ee];
__device__ __align__(16) __nv_bfloat16 g_Bhi[WTOT];
__device__ __align__(16) __nv_bfloat16 g_Blo[WTOT];

// ------------------------------ PTX helpers --------------------------------
__device__ __forceinline__ uint32_t smem_to_u32(const void* p) {
    uint32_t a;
    asm("{ .reg .u64 t; cvta.to.shared.u64 t, %1; cvt.u32.u64 %0, t; }"
        : "=r"(a) : "l"(p));
    return a;
}
__device__ __forceinline__ void ldsm_x4(uint32_t* r, uint32_t addr) {
    asm volatile("ldmatrix.sync.aligned.m8n8.x4.shared.b16 {%0,%1,%2,%3}, [%4];"
                 : "=r"(r[0]), "=r"(r[1]), "=r"(r[2]), "=r"(r[3]) : "r"(addr));
}
__device__ __forceinline__ void mma_bf16(float* c, const uint32_t* a, const uint32_t* b) {
    asm volatile(
        "mma.sync.aligned.m16n8k16.row.col.f32.bf16.bf16.f32 "
        "{%0,%1,%2,%3}, {%4,%5,%6,%7}, {%8,%9}, {%0,%1,%2,%3};"
        : "+f"(c[0]), "+f"(c[1]), "+f"(c[2]), "+f"(c[3])
        : "r"(a[0]), "r"(a[1]), "r"(a[2]), "r"(a[3]), "r"(b[0]), "r"(b[1]));
}
__device__ __forceinline__ void cp16(uint32_t saddr, const void* g) {
    asm volatile("cp.async.cg.shared.global [%0], [%1], 16;"
                 :: "r"(saddr), "l"(g) : "memory");
}
#define CP_COMMIT() asm volatile("cp.async.commit_group;" ::: "memory")
#define CP_WAIT0()  asm volatile("cp.async.wait_group 0;" ::: "memory")

__device__ __forceinline__ uint32_t pack_hilo(float a, float b, uint32_t& lopack) {
    __nv_bfloat16 ha = __float2bfloat16(a);
    __nv_bfloat16 hb = __float2bfloat16(b);
    float la = a - __bfloat162float(ha);
    float lb = b - __bfloat162float(hb);
    __nv_bfloat16 lah = __float2bfloat16(la);
    __nv_bfloat16 lbh = __float2bfloat16(lb);
    lopack = ((uint32_t)__bfloat16_as_ushort(lbh) << 16) | (uint32_t)__bfloat16_as_ushort(lah);
    return ((uint32_t)__bfloat16_as_ushort(hb) << 16) | (uint32_t)__bfloat16_as_ushort(ha);
}
__device__ __forceinline__ float2 bf2_to_f2(uint32_t u) {
    __nv_bfloat162 b = *reinterpret_cast<__nv_bfloat162*>(&u);
    return __bfloat1622float2(b);
}

// ----------------------------- CSR construction ----------------------------
__global__ void k_zero_cnt() {
    int i = blockIdx.x * blockDim.x + threadIdx.x;
    if (i < Nn) g_cnt[i] = 0;
}
__global__ void k_hist(const int* __restrict__ dst) {
    int i = blockIdx.x * blockDim.x + threadIdx.x;
    if (i < Ee) atomicAdd(&g_cnt[dst[i]], 1);
}
__global__ void k_scan() {
    __shared__ int sums[1024];
    const int t = threadIdx.x;
    const int CH = 128;
    const int base = t * CH;
    int s = 0;
    for (int i = 0; i < CH; i++) {
        int idx = base + i;
        if (idx < Nn) s += g_cnt[idx];
    }
    sums[t] = s;
    __syncthreads();
    int mine = s;
    for (int d = 1; d < 1024; d <<= 1) {
        int v = (t >= d) ? sums[t - d] : 0;
        __syncthreads();
        sums[t] += v;
        __syncthreads();
    }
    int run = sums[t] - mine;
    for (int i = 0; i < CH; i++) {
        int idx = base + i;
        if (idx < Nn) {
            int c = g_cnt[idx];
            g_rowptr[idx] = run;
            g_cursor[idx] = run;
            g_invdeg[idx] = 1.0f / fmaxf((float)c, 1.0f);
            run += c;
        }
    }
    if (t == 0) g_rowptr[Nn] = Ee;
}
__global__ void k_fill(const int* __restrict__ src, const int* __restrict__ dst) {
    int i = blockIdx.x * blockDim.x + threadIdx.x;
    if (i < Ee) {
        int d = dst[i];
        int pos = atomicAdd(&g_cursor[d], 1);
        g_csr[pos] = src[i];
    }
}

// ---------- mean aggregation (warp / node, hi plane only, 256B/edge) -------
// lane l covers block b = l>>2, cols b*16 + (l&3)*4 .. +3 (hi bytes (l&3)*8).
__global__ __launch_bounds__(256) void k_agg(const uint4* __restrict__ hp) {
    int warp = (blockIdx.x * blockDim.x + threadIdx.x) >> 5;
    if (warp >= Nn) return;
    int lane = threadIdx.x & 31;
    const char* base = (const char*)hp;
    const uint32_t loff = (uint32_t)((lane >> 2) * 64 + (lane & 3) * 8);
    int b = g_rowptr[warp];
    int e = g_rowptr[warp + 1];
    float a0 = 0.f, a1 = 0.f, a2 = 0.f, a3 = 0.f;
    int i = b;
    for (; i + 3 < e; i += 4) {
        int s0 = g_csr[i], s1 = g_csr[i + 1], s2 = g_csr[i + 2], s3 = g_csr[i + 3];
        uint2 u0 = *(const uint2*)(base + (size_t)s0 * 512 + loff);
        uint2 u1 = *(const uint2*)(base + (size_t)s1 * 512 + loff);
        uint2 u2 = *(const uint2*)(base + (size_t)s2 * 512 + loff);
        uint2 u3 = *(const uint2*)(base + (size_t)s3 * 512 + loff);
        float2 f;
        f = bf2_to_f2(u0.x); a0 += f.x; a1 += f.y;
        f = bf2_to_f2(u0.y); a2 += f.x; a3 += f.y;
        f = bf2_to_f2(u1.x); a0 += f.x; a1 += f.y;
        f = bf2_to_f2(u1.y); a2 += f.x; a3 += f.y;
        f = bf2_to_f2(u2.x); a0 += f.x; a1 += f.y;
        f = bf2_to_f2(u2.y); a2 += f.x; a3 += f.y;
        f = bf2_to_f2(u3.x); a0 += f.x; a1 += f.y;
        f = bf2_to_f2(u3.y); a2 += f.x; a3 += f.y;
    }
    for (; i < e; i++) {
        int s0 = g_csr[i];
        uint2 u0 = *(const uint2*)(base + (size_t)s0 * 512 + loff);
        float2 f;
        f = bf2_to_f2(u0.x); a0 += f.x; a1 += f.y;
        f = bf2_to_f2(u0.y); a2 += f.x; a3 += f.y;
    }
    float id = g_invdeg[warp];
    a0 *= id; a1 *= id; a2 *= id; a3 *= id;
    uint32_t lo0, lo1;
    uint32_t hi0 = pack_hilo(a0, a1, lo0);
    uint32_t hi1 = pack_hilo(a2, a3, lo1);
    char* ob = (char*)g_mp + (size_t)warp * 512 + loff;
    *(uint2*)ob = make_uint2(hi0, hi1);
    *(uint2*)(ob + 32) = make_uint2(lo0, lo1);
}

// ------------------------ conversions (weights, x) --------------------------
__global__ void k_wconv(const float* __restrict__ Wp, const float* __restrict__ Wl_h,
                        const float* __restrict__ Wr_h, const float* __restrict__ Wl_o,
                        const float* __restrict__ Wr_o) {
    int i = blockIdx.x * blockDim.x + threadIdx.x;
    if (i >= WTOT) return;
    float w;
    if (i < WOFF_H) {
        w = Wp[i];
    } else if (i < WOFF_O) {
        int j = i - WOFF_H;
        int layer = j / 32768;
        int r = j % 32768;
        int n = r >> 8, k = r & 255;
        w = (k < 128) ? Wl_h[layer * 16384 + n * 128 + k]
                      : Wr_h[layer * 16384 + n * 128 + (k - 128)];
    } else {
        int r = i - WOFF_O;
        int n = r >> 8, k = r & 255;
        w = (k < 128) ? Wl_o[n * 128 + k] : Wr_o[n * 128 + (k - 128)];
    }
    __nv_bfloat16 h = __float2bfloat16(w);
    g_Bhi[i] = h;
    g_Blo[i] = __float2bfloat16(w - __bfloat162float(h));
}

__global__ void k_xconv(const float* __restrict__ x) {
    int i = blockIdx.x * blockDim.x + threadIdx.x;
    if (i >= Nn * 32) return;
    int row = i >> 5, g = i & 31;
    int blk = g >> 2, quad = g & 3;
    const float4 f = *(const float4*)(x + (size_t)row * 128 + g * 4);
    uint32_t lo0, lo1;
    uint32_t hi0 = pack_hilo(f.x, f.y, lo0);
    uint32_t hi1 = pack_hilo(f.z, f.w, lo1);
    char* rb = (char*)g_xp + (size_t)row * 512 + blk * 64 + quad * 8;
    *(uint2*)rb = make_uint2(hi0, hi1);
    *(uint2*)(rb + 32) = make_uint2(lo0, lo1);
}

// ----------------------- smem-fed mma.sync bf16x3 GEMM ---------------------
// CTA m128 x nNOUT, 512 threads = 16 warps (8m x 2n), warp m16 x n(NOUT/2).
// A: block-packed activations staged whole-phase via cp.async (L1 bypass).
// B: bf16 hi/lo weights staged per phase. All mma operands via ldmatrix.
template <int NOUT, int NPH, bool RELU, bool RESID, bool PRE, bool WM, bool WPK>
__global__ __launch_bounds__(512, 1) void k_mgemm(
    const uint4* __restrict__ A0, const uint4* __restrict__ A1,
    const __nv_bfloat16* __restrict__ Bh, const __nv_bfloat16* __restrict__ Bl,
    const float* __restrict__ bias, const float* __restrict__ resid,
    float* __restrict__ outm, float* __restrict__ outp, uint4* __restrict__ outpk) {
    extern __shared__ char smem[];
    constexpr int ASZ = 128 * 528;           // A plane (rows pitch 528B)
    constexpr int OFF_B = NPH * ASZ;
    constexpr int BPL = NOUT * 272;          // B plane (rows pitch 272B)
    constexpr int OFF_BIAS = OFF_B + 2 * BPL;
    constexpr int KTOT = NPH * 128;
    constexpr int NI = NOUT / 16;            // n8 tiles per warp (8 or 4)
    constexpr int NW = NI * 8;

    const uint32_t sm32 = smem_to_u32(smem);
    const int tid = threadIdx.x;
    const int lane = tid & 31;
    const int wid = tid >> 5;
    const int wm = wid & 7;                  // m block (16 rows)
    const int wn = wid >> 3;                 // n block (NW cols)
    const int m0 = blockIdx.x * 128;

    // ---- stage all A phases + B phase 0 ----
#pragma unroll
    for (int p = 0; p < NPH; p++) {
        const uint4* Ap = (p ? A1 : A0) + (size_t)m0 * 32;
        for (int g = tid; g < 4096; g += 512) {
            int r = g >> 5, c = g & 31;
            cp16(sm32 + p * ASZ + r * 528 + c * 16, Ap + r * 32 + c);
        }
    }
    for (int g = tid; g < NOUT * 16; g += 512) {
        int n = g >> 4, c = g & 15;
        cp16(sm32 + OFF_B + n * 272 + c * 16, Bh + (size_t)n * KTOT + c * 8);
        cp16(sm32 + OFF_B + BPL + n * 272 + c * 16, Bl + (size_t)n * KTOT + c * 8);
    }
    CP_COMMIT();
    if (tid < NOUT) *(float*)(smem + OFF_BIAS + tid * 4) = bias[tid];
    CP_WAIT0();
    __syncthreads();

    const int r8 = lane & 7, q = lane >> 3;
    // A ldmatrix lane addr: rows wm*16 + (q&1)*8 + r8, k-half (q>>1)
    const uint32_t aoff =
        (uint32_t)((wm * 16 + (q & 1) * 8 + r8) * 528 + (q >> 1) * 16);
    // B ldmatrix lane addr
    const uint32_t boff =
        (uint32_t)((wn * NW + (q >> 1) * 8 + r8) * 272 + (q & 1) * 16);
    const uint32_t bBaseH = sm32 + OFF_B + boff;
    const uint32_t bBaseL = bBaseH + BPL;

    float acc[NI][4];
#pragma unroll
    for (int ni = 0; ni < NI; ni++)
#pragma unroll
        for (int c = 0; c < 4; c++) acc[ni][c] = 0.f;

#pragma unroll
    for (int p = 0; p < NPH; p++) {
        if (p > 0) {
            __syncthreads();
            for (int g = tid; g < NOUT * 16; g += 512) {
                int n = g >> 4, c = g & 15;
                cp16(sm32 + OFF_B + n * 272 + c * 16,
                     Bh + (size_t)n * KTOT + p * 128 + c * 8);
                cp16(sm32 + OFF_B + BPL + n * 272 + c * 16,
                     Bl + (size_t)n * KTOT + p * 128 + c * 8);
            }
            CP_COMMIT();
            CP_WAIT0();
            __syncthreads();
        }
        const uint32_t aBase = sm32 + (uint32_t)(p * ASZ) + aoff;
#pragma unroll
        for (int kb = 0; kb < 8; kb++) {
            uint32_t ah[4], al[4];
            ldsm_x4(ah, aBase + kb * 64);
            ldsm_x4(al, aBase + kb * 64 + 32);
            uint32_t bhf[NI / 2][4];
#pragma unroll
            for (int nt = 0; nt < NI / 2; nt++)
                ldsm_x4(bhf[nt], bBaseH + nt * 16 * 272 + kb * 32);
#pragma unroll
            for (int ni = 0; ni < NI; ni++)
                mma_bf16(acc[ni], ah, &bhf[ni >> 1][(ni & 1) * 2]);
            uint32_t blf[NI / 2][4];
#pragma unroll
            for (int nt = 0; nt < NI / 2; nt++)
                ldsm_x4(blf[nt], bBaseL + nt * 16 * 272 + kb * 32);
#pragma unroll
            for (int ni = 0; ni < NI; ni++)
                mma_bf16(acc[ni], al, &bhf[ni >> 1][(ni & 1) * 2]);
#pragma unroll
            for (int ni = 0; ni < NI; ni++)
                mma_bf16(acc[ni], ah, &blf[ni >> 1][(ni & 1) * 2]);
        }
    }

    // ------------------------------ epilogue -------------------------------
    const float* biasS = (const float*)(smem + OFF_BIAS);
    const int q4 = lane & 3;
    const int rbase = m0 + wm * 16 + (lane >> 2);
#pragma unroll
    for (int ni = 0; ni < NI; ni++) {
        const int col = wn * NW + ni * 8 + q4 * 2;
        const float b0 = biasS[col], b1 = biasS[col + 1];
#pragma unroll
        for (int half = 0; half < 2; half++) {
            const int row = rbase + half * 8;
            float x0 = acc[ni][half * 2 + 0] + b0;
            float x1 = acc[ni][half * 2 + 1] + b1;
            if (PRE) *(float2*)(outp + (size_t)row * 128 + col) = make_float2(x0, x1);
            if (RELU) { x0 = fmaxf(x0, 0.f); x1 = fmaxf(x1, 0.f); }
            if (RESID) {
                float2 rr = *(const float2*)(resid + (size_t)row * 128 + col);
                x0 = fmaf(0.2f, rr.x, x0);
                x1 = fmaf(0.2f, rr.y, x1);
            }
            if (WM) {
                if (row < Nn)
                    *(float2*)(outm + (size_t)row * NOUT + col) = make_float2(x0, x1);
            }
            if (WPK) {
                char* rb = (char*)outpk + (size_t)row * 512 + (col >> 4) * 64 +
                           (col & 15) * 2;
                uint32_t lo;
                uint32_t hi = pack_hilo(x0, x1, lo);
                *(uint32_t*)rb = hi;
                *(uint32_t*)(rb + 32) = lo;
            }
        }
    }
}

// ------------------------------ log-softmax --------------------------------
__global__ __launch_bounds__(256) void k_lsm(float* __restrict__ out) {
    int warp = (blockIdx.x * blockDim.x + threadIdx.x) >> 5;
    if (warp >= Nn) return;
    int lane = threadIdx.x & 31;
    float2 v = *(float2*)(out + (size_t)warp * Oc + lane * 2);
    float m = fmaxf(v.x, v.y);
#pragma unroll
    for (int o = 16; o; o >>= 1) m = fmaxf(m, __shfl_xor_sync(0xFFFFFFFFu, m, o));
    float s = expf(v.x - m) + expf(v.y - m);
#pragma unroll
    for (int o = 16; o; o >>= 1) s += __shfl_xor_sync(0xFFFFFFFFu, s, o);
    float l = m + logf(s);
    v.x -= l;
    v.y -= l;
    *(float2*)(out + (size_t)warp * Oc + lane * 2) = v;
}

// ------------------------------- launcher ----------------------------------
extern "C" void kernel_launch(void* const* d_in, const int* in_sizes, int n_in,
                              void* d_out, int out_size) {
    const float* x    = (const float*)d_in[0];
    const int*   ei   = (const int*)d_in[1];
    const float* Wp   = (const float*)d_in[2];
    const float* bp   = (const float*)d_in[3];
    const float* Wl_h = (const float*)d_in[4];
    const float* bl_h = (const float*)d_in[5];
    const float* Wr_h = (const float*)d_in[6];
    const float* Wl_o = (const float*)d_in[7];
    const float* bl_o = (const float*)d_in[8];
    const float* Wr_o = (const float*)d_in[9];
    const int* src = ei;
    const int* dst = ei + Ee;
    float* out = (float*)d_out;

    float* p_inp;
    cudaGetSymbolAddress((void**)&p_inp, g_inp);
    uint4 *p_xp, *p_hp0, *p_hp1, *p_mp;
    cudaGetSymbolAddress((void**)&p_xp, g_xp);
    cudaGetSymbolAddress((void**)&p_hp0, g_hp0);
    cudaGetSymbolAddress((void**)&p_hp1, g_hp1);
    cudaGetSymbolAddress((void**)&p_mp, g_mp);
    __nv_bfloat16 *p_bhi, *p_blo;
    cudaGetSymbolAddress((void**)&p_bhi, g_Bhi);
    cudaGetSymbolAddress((void**)&p_blo, g_Blo);

    auto gemm_in  = k_mgemm<128, 1, true, false, true, false, true>;
    auto gemm_hid = k_mgemm<128, 2, true, true, false, false, true>;
    auto gemm_out = k_mgemm<64, 2, false, false, false, true, false>;
    const int SM_IN  = 1 * 128 * 528 + 2 * 128 * 272 + 512;  // 137728
    const int SM_HID = 2 * 128 * 528 + 2 * 128 * 272 + 512;  // 205312
    const int SM_OUT = 2 * 128 * 528 + 2 * 64 * 272 + 256;   // 170240
    cudaFuncSetAttribute(gemm_in, cudaFuncAttributeMaxDynamicSharedMemorySize, SM_IN);
    cudaFuncSetAttribute(gemm_hid, cudaFuncAttributeMaxDynamicSharedMemorySize, SM_HID);
    cudaFuncSetAttribute(gemm_out, cudaFuncAttributeMaxDynamicSharedMemorySize, SM_OUT);

    // Launch order: ncu captures launch index 3 -> gemm_in.
    k_wconv<<<(WTOT + 255) / 256, 256>>>(Wp, Wl_h, Wr_h, Wl_o, Wr_o);          // 0
    k_xconv<<<(Nn * 32 + 255) / 256, 256>>>(x);                                // 1
    k_zero_cnt<<<(Nn + 255) / 256, 256>>>();                                   // 2
    gemm_in<<<NT, 512, SM_IN>>>(p_xp, nullptr, p_bhi + WOFF_IN, p_blo + WOFF_IN,  // 3
                                bp, nullptr, nullptr, p_inp, p_hp0);
    k_hist<<<(Ee + 255) / 256, 256>>>(dst);                                    // 4
    k_scan<<<1, 1024>>>();                                                     // 5
    k_fill<<<(Ee + 255) / 256, 256>>>(src, dst);                               // 6

    const int ga = ((Nn * 32) + 255) / 256;

    uint4 *hp = p_hp0, *np = p_hp1;
    for (int i = 0; i < 3; i++) {
        k_agg<<<ga, 256>>>(hp);
        gemm_hid<<<NT, 512, SM_HID>>>(p_mp, hp,
                                      p_bhi + WOFF_H + i * 32768, p_blo + WOFF_H + i * 32768,
                                      bl_h + (size_t)i * 128, p_inp,
                                      nullptr, nullptr, np);
        uint4* t = hp; hp = np; np = t;
    }

    k_agg<<<ga, 256>>>(hp);
    gemm_out<<<NT, 512, SM_OUT>>>(p_mp, hp, p_bhi + WOFF_O, p_blo + WOFF_O,
                                  bl_o, nullptr, out, nullptr, nullptr);
    k_lsm<<<ga, 256>>>(out);
}

// round 9
// speedup vs baseline: 1.2030x; 1.0040x over previous
#include <cuda_runtime.h>
#include <cuda_bf16.h>
#include <cstdint>

// ---------------------------------------------------------------------------
// GraphSAGE forward on GB300 — smem-fed mma.sync bf16x3 GEMMs (8 warps,
// m64xn32 warp tiles, smem-traffic-balanced) + hi-plane CSR mean aggregation.
// Activation row layout (128 cols, 512B): 8 k-blocks x [32B hi | 32B lo].
// ---------------------------------------------------------------------------
namespace {
constexpr int Nn = 100000;   // nodes
constexpr int Ee = 1600000;  // edges
constexpr int Hc = 128;      // hidden channels
constexpr int Oc = 64;       // out channels
constexpr int NP = 100096;   // padded rows (multiple of 128)
constexpr int NT = NP / 128; // 782 CTA tiles
// weight scratch layout (combined [Wl|Wr] per layer, row-major [n][k])
constexpr int WOFF_IN = 0;
constexpr int WOFF_H = 16384;
constexpr int WOFF_O = 16384 + 3 * 32768;
constexpr int WTOT = WOFF_O + 64 * 256;  // 131072
}

// ------------------------- static device scratch ---------------------------
__device__ float g_inp[(size_t)NP * Hc];   // pre-relu inProj (residual)
__device__ uint4 g_xp[(size_t)NP * 32];    // x packed (block hi/lo)
__device__ uint4 g_hp0[(size_t)NP * 32];   // h packed ping
__device__ uint4 g_hp1[(size_t)NP * 32];   // h packed pong
__device__ uint4 g_mp[(size_t)NP * 32];    // mean packed
__device__ float g_invdeg[Nn];
__device__ int   g_cnt[Nn];
__device__ int   g_rowptr[Nn + 1];
__device__ int   g_cursor[Nn];
__device__ int   g_csr[Ee];
__device__ __align__(16) __nv_bfloat16 g_Bhi[WTOT];
__device__ __align__(16) __nv_bfloat16 g_Blo[WTOT];

// ------------------------------ PTX helpers --------------------------------
__device__ __forceinline__ uint32_t smem_to_u32(const void* p) {
    uint32_t a;
    asm("{ .reg .u64 t; cvta.to.shared.u64 t, %1; cvt.u32.u64 %0, t; }"
        : "=r"(a) : "l"(p));
    return a;
}
__device__ __forceinline__ void ldsm_x4(uint32_t* r, uint32_t addr) {
    asm volatile("ldmatrix.sync.aligned.m8n8.x4.shared.b16 {%0,%1,%2,%3}, [%4];"
                 : "=r"(r[0]), "=r"(r[1]), "=r"(r[2]), "=r"(r[3]) : "r"(addr));
}
__device__ __forceinline__ void mma_bf16(float* c, const uint32_t* a, const uint32_t* b) {
    asm volatile(
        "mma.sync.aligned.m16n8k16.row.col.f32.bf16.bf16.f32 "
        "{%0,%1,%2,%3}, {%4,%5,%6,%7}, {%8,%9}, {%0,%1,%2,%3};"
        : "+f"(c[0]), "+f"(c[1]), "+f"(c[2]), "+f"(c[3])
        : "r"(a[0]), "r"(a[1]), "r"(a[2]), "r"(a[3]), "r"(b[0]), "r"(b[1]));
}
__device__ __forceinline__ void cp16(uint32_t saddr, const void* g) {
    asm volatile("cp.async.cg.shared.global [%0], [%1], 16;"
                 :: "r"(saddr), "l"(g) : "memory");
}
#define CP_COMMIT() asm volatile("cp.async.commit_group;" ::: "memory")
#define CP_WAIT0()  asm volatile("cp.async.wait_group 0;" ::: "memory")

__device__ __forceinline__ uint32_t pack_hilo(float a, float b, uint32_t& lopack) {
    __nv_bfloat16 ha = __float2bfloat16(a);
    __nv_bfloat16 hb = __float2bfloat16(b);
    float la = a - __bfloat162float(ha);
    float lb = b - __bfloat162float(hb);
    __nv_bfloat16 lah = __float2bfloat16(la);
    __nv_bfloat16 lbh = __float2bfloat16(lb);
    lopack = ((uint32_t)__bfloat16_as_ushort(lbh) << 16) | (uint32_t)__bfloat16_as_ushort(lah);
    return ((uint32_t)__bfloat16_as_ushort(hb) << 16) | (uint32_t)__bfloat16_as_ushort(ha);
}
__device__ __forceinline__ float2 bf2_to_f2(uint32_t u) {
    __nv_bfloat162 b = *reinterpret_cast<__nv_bfloat162*>(&u);
    return __bfloat1622float2(b);
}

// ----------------------------- CSR construction ----------------------------
__global__ void k_zero_cnt() {
    int i = blockIdx.x * blockDim.x + threadIdx.x;
    if (i < Nn) g_cnt[i] = 0;
}
__global__ void k_hist(const int* __restrict__ dst) {
    int i = blockIdx.x * blockDim.x + threadIdx.x;
    if (i < Ee) atomicAdd(&g_cnt[dst[i]], 1);
}
__global__ void k_scan() {
    __shared__ int sums[1024];
    const int t = threadIdx.x;
    const int CH = 128;
    const int base = t * CH;
    int s = 0;
    for (int i = 0; i < CH; i++) {
        int idx = base + i;
        if (idx < Nn) s += g_cnt[idx];
    }
    sums[t] = s;
    __syncthreads();
    int mine = s;
    for (int d = 1; d < 1024; d <<= 1) {
        int v = (t >= d) ? sums[t - d] : 0;
        __syncthreads();
        sums[t] += v;
        __syncthreads();
    }
    int run = sums[t] - mine;
    for (int i = 0; i < CH; i++) {
        int idx = base + i;
        if (idx < Nn) {
            int c = g_cnt[idx];
            g_rowptr[idx] = run;
            g_cursor[idx] = run;
            g_invdeg[idx] = 1.0f / fmaxf((float)c, 1.0f);
            run += c;
        }
    }
    if (t == 0) g_rowptr[Nn] = Ee;
}
__global__ void k_fill(const int* __restrict__ src, const int* __restrict__ dst) {
    int i = blockIdx.x * blockDim.x + threadIdx.x;
    if (i < Ee) {
        int d = dst[i];
        int pos = atomicAdd(&g_cursor[d], 1);
        g_csr[pos] = src[i];
    }
}

// ---------- mean aggregation (warp / node, hi plane only, 256B/edge) -------
__global__ __launch_bounds__(256) void k_agg(const uint4* __restrict__ hp) {
    int warp = (blockIdx.x * blockDim.x + threadIdx.x) >> 5;
    if (warp >= Nn) return;
    int lane = threadIdx.x & 31;
    const char* base = (const char*)hp;
    const uint32_t loff = (uint32_t)((lane >> 2) * 64 + (lane & 3) * 8);
    int b = g_rowptr[warp];
    int e = g_rowptr[warp + 1];
    float a0 = 0.f, a1 = 0.f, a2 = 0.f, a3 = 0.f;
    int i = b;
    for (; i + 7 < e; i += 8) {
        uint2 u[8];
#pragma unroll
        for (int j = 0; j < 8; j++)
            u[j] = *(const uint2*)(base + (size_t)g_csr[i + j] * 512 + loff);
#pragma unroll
        for (int j = 0; j < 8; j++) {
            float2 f;
            f = bf2_to_f2(u[j].x); a0 += f.x; a1 += f.y;
            f = bf2_to_f2(u[j].y); a2 += f.x; a3 += f.y;
        }
    }
    for (; i < e; i++) {
        uint2 u0 = *(const uint2*)(base + (size_t)g_csr[i] * 512 + loff);
        float2 f;
        f = bf2_to_f2(u0.x); a0 += f.x; a1 += f.y;
        f = bf2_to_f2(u0.y); a2 += f.x; a3 += f.y;
    }
    float id = g_invdeg[warp];
    a0 *= id; a1 *= id; a2 *= id; a3 *= id;
    uint32_t lo0, lo1;
    uint32_t hi0 = pack_hilo(a0, a1, lo0);
    uint32_t hi1 = pack_hilo(a2, a3, lo1);
    char* ob = (char*)g_mp + (size_t)warp * 512 + loff;
    *(uint2*)ob = make_uint2(hi0, hi1);
    *(uint2*)(ob + 32) = make_uint2(lo0, lo1);
}

// ------------------------ conversions (weights, x) --------------------------
__global__ void k_wconv(const float* __restrict__ Wp, const float* __restrict__ Wl_h,
                        const float* __restrict__ Wr_h, const float* __restrict__ Wl_o,
                        const float* __restrict__ Wr_o) {
    int i = blockIdx.x * blockDim.x + threadIdx.x;
    if (i >= WTOT) return;
    float w;
    if (i < WOFF_H) {
        w = Wp[i];
    } else if (i < WOFF_O) {
        int j = i - WOFF_H;
        int layer = j / 32768;
        int r = j % 32768;
        int n = r >> 8, k = r & 255;
        w = (k < 128) ? Wl_h[layer * 16384 + n * 128 + k]
                      : Wr_h[layer * 16384 + n * 128 + (k - 128)];
    } else {
        int r = i - WOFF_O;
        int n = r >> 8, k = r & 255;
        w = (k < 128) ? Wl_o[n * 128 + k] : Wr_o[n * 128 + (k - 128)];
    }
    __nv_bfloat16 h = __float2bfloat16(w);
    g_Bhi[i] = h;
    g_Blo[i] = __float2bfloat16(w - __bfloat162float(h));
}

__global__ void k_xconv(const float* __restrict__ x) {
    int i = blockIdx.x * blockDim.x + threadIdx.x;
    if (i >= Nn * 32) return;
    int row = i >> 5, g = i & 31;
    int blk = g >> 2, quad = g & 3;
    const float4 f = *(const float4*)(x + (size_t)row * 128 + g * 4);
    uint32_t lo0, lo1;
    uint32_t hi0 = pack_hilo(f.x, f.y, lo0);
    uint32_t hi1 = pack_hilo(f.z, f.w, lo1);
    char* rb = (char*)g_xp + (size_t)row * 512 + blk * 64 + quad * 8;
    *(uint2*)rb = make_uint2(hi0, hi1);
    *(uint2*)(rb + 32) = make_uint2(lo0, lo1);
}

// ----------------------- smem-fed mma.sync bf16x3 GEMM ---------------------
// CTA m128 x nNOUT, 256 threads = 8 warps (2m x 4n), warp m64 x n(NOUT/4).
// Smem traffic balanced with HMMA demand (A re-read x4, B re-read x2).
template <int NOUT, int NPH, bool RELU, bool RESID, bool PRE, bool WM, bool WPK>
__global__ __launch_bounds__(256, 1) void k_mgemm(
    const uint4* __restrict__ A0, const uint4* __restrict__ A1,
    const __nv_bfloat16* __restrict__ Bh, const __nv_bfloat16* __restrict__ Bl,
    const float* __restrict__ bias, const float* __restrict__ resid,
    float* __restrict__ outm, float* __restrict__ outp, uint4* __restrict__ outpk) {
    extern __shared__ char smem[];
    constexpr int ASZ = 128 * 528;           // A plane (rows pitch 528B)
    constexpr int OFF_B = NPH * ASZ;
    constexpr int BPL = NOUT * 272;          // B plane (rows pitch 272B)
    constexpr int OFF_BIAS = OFF_B + 2 * BPL;
    constexpr int KTOT = NPH * 128;
    constexpr int NW = NOUT / 4;             // warp n width (32 or 16)
    constexpr int NI = NW / 8;               // n8 tiles per warp (4 or 2)
    constexpr int NT16 = NW / 16;            // n16 tiles per warp (2 or 1)

    const uint32_t sm32 = smem_to_u32(smem);
    const int tid = threadIdx.x;
    const int lane = tid & 31;
    const int wid = tid >> 5;
    const int wm = wid & 1;                  // m block (64 rows)
    const int wn = wid >> 1;                 // n block (NW cols)
    const int m0 = blockIdx.x * 128;

    // ---- stage all A phases + B phase 0 ----
#pragma unroll
    for (int p = 0; p < NPH; p++) {
        const uint4* Ap = (p ? A1 : A0) + (size_t)m0 * 32;
        for (int g = tid; g < 4096; g += 256) {
            int r = g >> 5, c = g & 31;
            cp16(sm32 + p * ASZ + r * 528 + c * 16, Ap + r * 32 + c);
        }
    }
    for (int g = tid; g < NOUT * 16; g += 256) {
        int n = g >> 4, c = g & 15;
        cp16(sm32 + OFF_B + n * 272 + c * 16, Bh + (size_t)n * KTOT + c * 8);
        cp16(sm32 + OFF_B + BPL + n * 272 + c * 16, Bl + (size_t)n * KTOT + c * 8);
    }
    CP_COMMIT();
    if (tid < NOUT) *(float*)(smem + OFF_BIAS + tid * 4) = bias[tid];
    CP_WAIT0();
    __syncthreads();

    const int r8 = lane & 7, q = lane >> 3;
    // A ldmatrix lane addr (m16 tile mi at +mi*16 rows)
    const uint32_t aoff =
        (uint32_t)((wm * 64 + (q & 1) * 8 + r8) * 528 + (q >> 1) * 16);
    // B ldmatrix lane addr (n16 tile nt at +nt*16 rows)
    const uint32_t boff =
        (uint32_t)((wn * NW + (q >> 1) * 8 + r8) * 272 + (q & 1) * 16);
    const uint32_t bBaseH = sm32 + OFF_B + boff;
    const uint32_t bBaseL = bBaseH + BPL;

    float acc[4][NI][4];
#pragma unroll
    for (int mi = 0; mi < 4; mi++)
#pragma unroll
        for (int ni = 0; ni < NI; ni++)
#pragma unroll
            for (int c = 0; c < 4; c++) acc[mi][ni][c] = 0.f;

#pragma unroll
    for (int p = 0; p < NPH; p++) {
        if (p > 0) {
            __syncthreads();
            for (int g = tid; g < NOUT * 16; g += 256) {
                int n = g >> 4, c = g & 15;
                cp16(sm32 + OFF_B + n * 272 + c * 16,
                     Bh + (size_t)n * KTOT + p * 128 + c * 8);
                cp16(sm32 + OFF_B + BPL + n * 272 + c * 16,
                     Bl + (size_t)n * KTOT + p * 128 + c * 8);
            }
            CP_COMMIT();
            CP_WAIT0();
            __syncthreads();
        }
        const uint32_t aBase = sm32 + (uint32_t)(p * ASZ) + aoff;
#pragma unroll
        for (int kb = 0; kb < 8; kb++) {
            uint32_t ah[4][4], al[4][4];
#pragma unroll
            for (int mi = 0; mi < 4; mi++) {
                ldsm_x4(ah[mi], aBase + mi * 16 * 528 + kb * 64);
                ldsm_x4(al[mi], aBase + mi * 16 * 528 + kb * 64 + 32);
            }
            uint32_t bhf[NT16][4], blf[NT16][4];
#pragma unroll
            for (int nt = 0; nt < NT16; nt++) {
                ldsm_x4(bhf[nt], bBaseH + nt * 16 * 272 + kb * 32);
                ldsm_x4(blf[nt], bBaseL + nt * 16 * 272 + kb * 32);
            }
            // pass 1: Ah * Bh
#pragma unroll
            for (int mi = 0; mi < 4; mi++)
#pragma unroll
                for (int ni = 0; ni < NI; ni++)
                    mma_bf16(acc[mi][ni], ah[mi], &bhf[ni >> 1][(ni & 1) * 2]);
            // pass 2: Al * Bh
#pragma unroll
            for (int mi = 0; mi < 4; mi++)
#pragma unroll
                for (int ni = 0; ni < NI; ni++)
                    mma_bf16(acc[mi][ni], al[mi], &bhf[ni >> 1][(ni & 1) * 2]);
            // pass 3: Ah * Bl
#pragma unroll
            for (int mi = 0; mi < 4; mi++)
#pragma unroll
                for (int ni = 0; ni < NI; ni++)
                    mma_bf16(acc[mi][ni], ah[mi], &blf[ni >> 1][(ni & 1) * 2]);
        }
    }

    // ------------------------------ epilogue -------------------------------
    const float* biasS = (const float*)(smem + OFF_BIAS);
    const int q4 = lane & 3;
    const int rbase = m0 + wm * 64 + (lane >> 2);
#pragma unroll
    for (int mi = 0; mi < 4; mi++) {
#pragma unroll
        for (int ni = 0; ni < NI; ni++) {
            const int col = wn * NW + ni * 8 + q4 * 2;
            const float b0 = biasS[col], b1 = biasS[col + 1];
#pragma unroll
            for (int half = 0; half < 2; half++) {
                const int row = rbase + mi * 16 + half * 8;
                float x0 = acc[mi][ni][half * 2 + 0] + b0;
                float x1 = acc[mi][ni][half * 2 + 1] + b1;
                if (PRE) *(float2*)(outp + (size_t)row * 128 + col) = make_float2(x0, x1);
                if (RELU) { x0 = fmaxf(x0, 0.f); x1 = fmaxf(x1, 0.f); }
                if (RESID) {
                    float2 rr = *(const float2*)(resid + (size_t)row * 128 + col);
                    x0 = fmaf(0.2f, rr.x, x0);
                    x1 = fmaf(0.2f, rr.y, x1);
                }
                if (WM) {
                    if (row < Nn)
                        *(float2*)(outm + (size_t)row * NOUT + col) = make_float2(x0, x1);
                }
                if (WPK) {
                    char* rb = (char*)outpk + (size_t)row * 512 + (col >> 4) * 64 +
                               (col & 15) * 2;
                    uint32_t lo;
                    uint32_t hi = pack_hilo(x0, x1, lo);
                    *(uint32_t*)rb = hi;
                    *(uint32_t*)(rb + 32) = lo;
                }
            }
        }
    }
}

// ------------------------------ log-softmax --------------------------------
__global__ __launch_bounds__(256) void k_lsm(float* __restrict__ out) {
    int warp = (blockIdx.x * blockDim.x + threadIdx.x) >> 5;
    if (warp >= Nn) return;
    int lane = threadIdx.x & 31;
    float2 v = *(float2*)(out + (size_t)warp * Oc + lane * 2);
    float m = fmaxf(v.x, v.y);
#pragma unroll
    for (int o = 16; o; o >>= 1) m = fmaxf(m, __shfl_xor_sync(0xFFFFFFFFu, m, o));
    float s = expf(v.x - m) + expf(v.y - m);
#pragma unroll
    for (int o = 16; o; o >>= 1) s += __shfl_xor_sync(0xFFFFFFFFu, s, o);
    float l = m + logf(s);
    v.x -= l;
    v.y -= l;
    *(float2*)(out + (size_t)warp * Oc + lane * 2) = v;
}

// ------------------------------- launcher ----------------------------------
extern "C" void kernel_launch(void* const* d_in, const int* in_sizes, int n_in,
                              void* d_out, int out_size) {
    const float* x    = (const float*)d_in[0];
    const int*   ei   = (const int*)d_in[1];
    const float* Wp   = (const float*)d_in[2];
    const float* bp   = (const float*)d_in[3];
    const float* Wl_h = (const float*)d_in[4];
    const float* bl_h = (const float*)d_in[5];
    const float* Wr_h = (const float*)d_in[6];
    const float* Wl_o = (const float*)d_in[7];
    const float* bl_o = (const float*)d_in[8];
    const float* Wr_o = (const float*)d_in[9];
    const int* src = ei;
    const int* dst = ei + Ee;
    float* out = (float*)d_out;

    float* p_inp;
    cudaGetSymbolAddress((void**)&p_inp, g_inp);
    uint4 *p_xp, *p_hp0, *p_hp1, *p_mp;
    cudaGetSymbolAddress((void**)&p_xp, g_xp);
    cudaGetSymbolAddress((void**)&p_hp0, g_hp0);
    cudaGetSymbolAddress((void**)&p_hp1, g_hp1);
    cudaGetSymbolAddress((void**)&p_mp, g_mp);
    __nv_bfloat16 *p_bhi, *p_blo;
    cudaGetSymbolAddress((void**)&p_bhi, g_Bhi);
    cudaGetSymbolAddress((void**)&p_blo, g_Blo);

    auto gemm_in  = k_mgemm<128, 1, true, false, true, false, true>;
    auto gemm_hid = k_mgemm<128, 2, true, true, false, false, true>;
    auto gemm_out = k_mgemm<64, 2, false, false, false, true, false>;
    const int SM_IN  = 1 * 128 * 528 + 2 * 128 * 272 + 512;  // 137728
    const int SM_HID = 2 * 128 * 528 + 2 * 128 * 272 + 512;  // 205312
    const int SM_OUT = 2 * 128 * 528 + 2 * 64 * 272 + 256;   // 170240
    cudaFuncSetAttribute(gemm_in, cudaFuncAttributeMaxDynamicSharedMemorySize, SM_IN);
    cudaFuncSetAttribute(gemm_hid, cudaFuncAttributeMaxDynamicSharedMemorySize, SM_HID);
    cudaFuncSetAttribute(gemm_out, cudaFuncAttributeMaxDynamicSharedMemorySize, SM_OUT);

    // Launch order: ncu captures launch index 3 -> gemm_in.
    k_wconv<<<(WTOT + 255) / 256, 256>>>(Wp, Wl_h, Wr_h, Wl_o, Wr_o);          // 0
    k_xconv<<<(Nn * 32 + 255) / 256, 256>>>(x);                                // 1
    k_zero_cnt<<<(Nn + 255) / 256, 256>>>();                                   // 2
    gemm_in<<<NT, 256, SM_IN>>>(p_xp, nullptr, p_bhi + WOFF_IN, p_blo + WOFF_IN,  // 3
                                bp, nullptr, nullptr, p_inp, p_hp0);
    k_hist<<<(Ee + 255) / 256, 256>>>(dst);                                    // 4
    k_scan<<<1, 1024>>>();                                                     // 5
    k_fill<<<(Ee + 255) / 256, 256>>>(src, dst);                               // 6

    const int ga = ((Nn * 32) + 255) / 256;

    uint4 *hp = p_hp0, *np = p_hp1;
    for (int i = 0; i < 3; i++) {
        k_agg<<<ga, 256>>>(hp);
        gemm_hid<<<NT, 256, SM_HID>>>(p_mp, hp,
                                      p_bhi + WOFF_H + i * 32768, p_blo + WOFF_H + i * 32768,
                                      bl_h + (size_t)i * 128, p_inp,
                                      nullptr, nullptr, np);
        uint4* t = hp; hp = np; np = t;
    }

    k_agg<<<ga, 256>>>(hp);
    gemm_out<<<NT, 256, SM_OUT>>>(p_mp, hp, p_bhi + WOFF_O, p_blo + WOFF_O,
                                  bl_o, nullptr, out, nullptr, nullptr);
    k_lsm<<<ga, 256>>>(out);
}